// round 12
// baseline (speedup 1.0000x reference)
#include <cuda_runtime.h>
#include <cuda_bf16.h>
#include <cstdint>

#define EN 8192
#define EL 8192
#define DD 256
#define NG 64
#define SLOTS 16

// ---------------- scratch (device globals) ----------------------------------
__device__ __align__(128) __nv_bfloat16 g_efn_bf[EN * DD];
__device__ __align__(128) __nv_bfloat16 g_efl_bf[EL * DD];
__device__ __align__(128) float    g_na[EN];
__device__ __align__(128) float    g_nb[EL];
__device__ __align__(128) unsigned g_rowmin[EN * NG];   // [i][gl]
__device__ __align__(128) unsigned g_colmin[NG * EL];   // [gn][j]
__device__ __align__(128) float    g_sumn[NG * NG];
__device__ __align__(128) float    g_suml[NG * NG];
__device__ __align__(128) int      g_cntn[NG];
__device__ __align__(128) int      g_cntl[NG];

__device__ __forceinline__ unsigned encf(float f) {
    unsigned u = __float_as_uint(f);
    return (u & 0x80000000u) ? ~u : (u | 0x80000000u);
}
__device__ __forceinline__ float decf(unsigned k) {
    unsigned u = (k & 0x80000000u) ? (k & 0x7FFFFFFFu) : ~k;
    return __uint_as_float(u);
}

#define SENTINEL 0xFFFFFFFFu
#define INF_F __int_as_float(0x7f800000)

// ---------------- kernel 0 ---------------------------------------------------
__global__ void init_mins_kernel() {
    int i = blockIdx.x * blockDim.x + threadIdx.x;
    if (i < EN * NG) {
        g_rowmin[i] = SENTINEL;
        g_colmin[i] = SENTINEL;
    }
    if (i < NG * NG) { g_sumn[i] = 0.f; g_suml[i] = 0.f; }
    if (i < NG)      { g_cntn[i] = 0;   g_cntl[i] = 0; }
}

// ---------------- kernel 1 ---------------------------------------------------
__global__ void build_ef_kernel(const float* __restrict__ h,
                                const int* __restrict__ edge,
                                int which) {
    __nv_bfloat16* ef = which ? g_efl_bf : g_efn_bf;
    float* nrm        = which ? g_nb     : g_na;
    int e = blockIdx.x;
    int t = threadIdx.x;
    int i0 = edge[e];
    int i1 = edge[EN + e];
    float v = 0.5f * (h[(size_t)i0 * DD + t] + h[(size_t)i1 * DD + t]);
    ef[(size_t)e * DD + t] = __float2bfloat16_rn(v);
    float s = v * v;
    #pragma unroll
    for (int o = 16; o > 0; o >>= 1) s += __shfl_down_sync(0xffffffffu, s, o);
    __shared__ float ws[8];
    if ((t & 31) == 0) ws[t >> 5] = s;
    __syncthreads();
    if (t < 8) {
        float x = ws[t];
        #pragma unroll
        for (int o = 4; o > 0; o >>= 1) x += __shfl_down_sync(0xffu, x, o);
        if (t == 0) nrm[e] = x;
    }
}

// ---------------- PTX helpers -------------------------------------------------
__device__ __forceinline__ void cp16(uint32_t dst, const void* src) {
    asm volatile("cp.async.cg.shared.global [%0], [%1], 16;" :: "r"(dst), "l"(src));
}
__device__ __forceinline__ void cp_commit() { asm volatile("cp.async.commit_group;"); }
__device__ __forceinline__ void cp_wait0()  { asm volatile("cp.async.wait_group 0;"); }
__device__ __forceinline__ void ldmx4(uint32_t* r, uint32_t addr) {
    asm volatile("ldmatrix.sync.aligned.m8n8.x4.shared.b16 {%0,%1,%2,%3}, [%4];"
                 : "=r"(r[0]), "=r"(r[1]), "=r"(r[2]), "=r"(r[3]) : "r"(addr));
}
__device__ __forceinline__ void mma16816(float* d, const uint32_t* a,
                                         uint32_t b0, uint32_t b1) {
    asm volatile("mma.sync.aligned.m16n8k16.row.col.f32.bf16.bf16.f32 "
                 "{%0,%1,%2,%3}, {%4,%5,%6,%7}, {%8,%9}, {%0,%1,%2,%3};"
                 : "+f"(d[0]), "+f"(d[1]), "+f"(d[2]), "+f"(d[3])
                 : "r"(a[0]), "r"(a[1]), "r"(a[2]), "r"(a[3]), "r"(b0), "r"(b1));
}

// ---------------- kernel 2: full-K mma.sync GEMM + fused group-min ----------
// 256 CTAs: cta -> (tileI = cta>>2, q = cta&3); each handles J tiles q*16..q*16+15.
// A stripe 128x256 loaded once; B tile 128x256 double-buffered; NO barriers
// inside the 16-step K loop -> ptxas can pipeline LDSM across the whole tile.
#define LDAE 264                      // 256 + 8 pad (bf16 elems); row = 528 B
#define ABYTES (128 * LDAE * 2)       // 67584

#define OFF_A    0
#define OFF_B0   67584
#define OFF_B1   135168
#define OFF_RM   202752
#define OFF_CM   210944
#define OFF_GLC  219136
#define OFF_SNB  220160
#define OFF_GNC  221184
#define SMEM_TC  (221696 + 1024)

__global__ void __launch_bounds__(256, 1)
gemm_fullk_kernel(const int* __restrict__ nbatch, const int* __restrict__ lbatch) {
    extern __shared__ char dsm_raw[];
    const uint32_t sraw = (uint32_t)__cvta_generic_to_shared(dsm_raw);
    const uint32_t s0 = (sraw + 1023u) & ~1023u;
    char* p0 = dsm_raw + (s0 - sraw);

    unsigned* rm  = (unsigned*)(p0 + OFF_RM);   // [128][SLOTS]
    unsigned* cm  = (unsigned*)(p0 + OFF_CM);   // [128][SLOTS]
    int*      glc = (int*)     (p0 + OFF_GLC);  // [2][128]
    float*    snb = (float*)   (p0 + OFF_SNB);  // [2][128]
    int*      gnc = (int*)     (p0 + OFF_GNC);  // [128]

    const int tid  = threadIdx.x;
    const int wid  = tid >> 5;
    const int lane = tid & 31;
    const int tileI = blockIdx.x >> 2;
    const int q     = blockIdx.x & 3;
    const int rowbase = tileI * 128;

    const int wr = wid & 1;
    const int wc = wid >> 1;
    const int wrBase = wr * 64;
    const int wcBase = wc * 32;

    // ldmatrix lane address components (R7-proven)
    const int aRow = (lane & 7) + ((lane >> 3) & 1) * 8;
    const int aK   = (lane >> 4) * 8;
    const int bRow = (lane & 7) + (lane >> 4) * 8;
    const int bK   = ((lane >> 3) & 1) * 8;

    // global->shared: 16 chunks of 16B per thread per 128x256 tile
    const int ldR = tid >> 1;           // unused helper removed; full mapping below

    // prologue: A stripe + B tile 0 + metadata
    #pragma unroll
    for (int it = 0; it < 16; ++it) {
        int id = it * 256 + tid;
        int r = id >> 5, kk = id & 31;
        cp16(s0 + OFF_A + (uint32_t)(r * LDAE + kk * 8) * 2,
             g_efn_bf + (size_t)(rowbase + r) * DD + kk * 8);
    }
    {
        int jb0 = (q * 16) * 128;
        #pragma unroll
        for (int it = 0; it < 16; ++it) {
            int id = it * 256 + tid;
            int r = id >> 5, kk = id & 31;
            cp16(s0 + OFF_B0 + (uint32_t)(r * LDAE + kk * 8) * 2,
                 g_efl_bf + (size_t)(jb0 + r) * DD + kk * 8);
        }
        if (tid < 128) {
            gnc[tid] = nbatch[rowbase + tid];
            glc[tid] = lbatch[jb0 + tid];
            snb[tid] = g_nb[jb0 + tid];
        }
    }
    cp_commit();
    (void)ldR;

    // per-warp row metadata (fixed across tiles)
    const int g  = lane >> 2;
    const int t2 = (lane & 3) * 2;
    int   lrows[8], grows[8];
    float nav[8];
    // (gnc not yet visible; compute after first sync)

    cp_wait0();
    __syncthreads();

    #pragma unroll
    for (int m = 0; m < 8; m++) {
        lrows[m] = wrBase + (m >> 1) * 16 + g + (m & 1) * 8;
        grows[m] = gnc[lrows[m]];
        nav[m]   = g_na[rowbase + lrows[m]];
    }
    const int  gn_lo = gnc[0];
    const bool fastN = (gnc[127] - gn_lo) < SLOTS;

    for (int t = 0; t < 16; ++t) {
        const int cur = t & 1;
        const int jbase = (q * 16 + t) * 128;

        // prefetch next B tile + metadata (overlaps this tile's compute)
        if (t > 0) { cp_wait0(); __syncthreads(); }   // B[cur] ready (prologue for t=0 already waited)
        if (t < 15) {
            int nxt = cur ^ 1;
            int jb1 = (q * 16 + t + 1) * 128;
            #pragma unroll
            for (int it = 0; it < 16; ++it) {
                int id = it * 256 + tid;
                int r = id >> 5, kk = id & 31;
                cp16(s0 + (nxt ? OFF_B1 : OFF_B0) + (uint32_t)(r * LDAE + kk * 8) * 2,
                     g_efl_bf + (size_t)(jb1 + r) * DD + kk * 8);
            }
            if (tid < 128) {
                glc[nxt * 128 + tid] = lbatch[jb1 + tid];
                snb[nxt * 128 + tid] = g_nb[jb1 + tid];
            }
            cp_commit();
        }

        // init staging (before compute; one sync covers it)
        #pragma unroll
        for (int x = tid; x < 128 * SLOTS; x += 256) { rm[x] = SENTINEL; cm[x] = SENTINEL; }
        __syncthreads();

        // ---- compute: full K=256, no barriers ----
        float c[4][4][4];
        #pragma unroll
        for (int mi = 0; mi < 4; mi++)
            #pragma unroll
            for (int ni = 0; ni < 4; ni++)
                #pragma unroll
                for (int qq = 0; qq < 4; qq++) c[mi][ni][qq] = 0.f;

        const uint32_t sA = s0 + OFF_A;
        const uint32_t sB = s0 + (cur ? OFF_B1 : OFF_B0);
        #pragma unroll
        for (int kb = 0; kb < 256; kb += 16) {
            uint32_t a[4][4];
            #pragma unroll
            for (int mi = 0; mi < 4; mi++)
                ldmx4(a[mi], sA + (uint32_t)((wrBase + mi * 16 + aRow) * LDAE + kb + aK) * 2);
            uint32_t b[2][4];
            #pragma unroll
            for (int nq = 0; nq < 2; nq++)
                ldmx4(b[nq], sB + (uint32_t)((wcBase + nq * 16 + bRow) * LDAE + kb + bK) * 2);
            #pragma unroll
            for (int mi = 0; mi < 4; mi++) {
                #pragma unroll
                for (int nq = 0; nq < 2; nq++) {
                    mma16816(c[mi][nq * 2 + 0], a[mi], b[nq][0], b[nq][1]);
                    mma16816(c[mi][nq * 2 + 1], a[mi], b[nq][2], b[nq][3]);
                }
            }
        }

        // ---- epilogue (R10-proven group-min) ----
        const int*   glcc = glc + cur * 128;
        const float* snbc = snb + cur * 128;
        const int  gl_lo = glcc[0];
        const bool fastL = (glcc[127] - gl_lo) < SLOTS;

        int   lcols[8], gcols[8];
        float nbv[8];
        #pragma unroll
        for (int n = 0; n < 8; n++) {
            lcols[n] = wcBase + (n >> 1) * 8 + t2 + (n & 1);
            gcols[n] = glcc[lcols[n]];
            nbv[n]   = snbc[lcols[n]];
        }

        // row-side
        #pragma unroll
        for (int m = 0; m < 8; m++) {
            const int mi = m >> 1, hh = m & 1;
            float rbest = INF_F;
            int curgl = -1;
            #pragma unroll
            for (int n = 0; n < 8; n++) {
                const int ni = n >> 1, u = n & 1;
                float rv = fmaf(-2.f, c[mi][ni][hh * 2 + u], nbv[n]);
                int gg = gcols[n];
                if (gg != curgl) {
                    if (curgl >= 0) {
                        unsigned k = encf(rbest);
                        if (fastL) atomicMin(&rm[lrows[m] * SLOTS + (curgl - gl_lo)], k);
                        else       atomicMin(&g_rowmin[(size_t)(rowbase + lrows[m]) * NG + curgl], k);
                    }
                    curgl = gg; rbest = rv;
                } else {
                    rbest = fminf(rbest, rv);
                }
            }
            unsigned k = encf(rbest);
            if (fastL) atomicMin(&rm[lrows[m] * SLOTS + (curgl - gl_lo)], k);
            else       atomicMin(&g_rowmin[(size_t)(rowbase + lrows[m]) * NG + curgl], k);
        }

        // col-side
        {
            float cb[8];
            #pragma unroll
            for (int n = 0; n < 8; n++) cb[n] = INF_F;
            int curgn = -1;
            #pragma unroll
            for (int m = 0; m < 8; m++) {
                const int mi = m >> 1, hh = m & 1;
                int gi = grows[m];
                if (gi != curgn) {
                    if (curgn >= 0) {
                        #pragma unroll
                        for (int n = 0; n < 8; n++) {
                            unsigned k = encf(cb[n]);
                            if (fastN) atomicMin(&cm[lcols[n] * SLOTS + (curgn - gn_lo)], k);
                            else       atomicMin(&g_colmin[(size_t)curgn * EL + jbase + lcols[n]], k);
                            cb[n] = INF_F;
                        }
                    }
                    curgn = gi;
                }
                #pragma unroll
                for (int n = 0; n < 8; n++) {
                    const int ni = n >> 1, u = n & 1;
                    cb[n] = fminf(cb[n], fmaf(-2.f, c[mi][ni][hh * 2 + u], nav[m]));
                }
            }
            #pragma unroll
            for (int n = 0; n < 8; n++) {
                unsigned k = encf(cb[n]);
                if (fastN) atomicMin(&cm[lcols[n] * SLOTS + (curgn - gn_lo)], k);
                else       atomicMin(&g_colmin[(size_t)curgn * EL + jbase + lcols[n]], k);
            }
        }
        __syncthreads();

        // flush staging (R7/R10-proven pattern)
        if (fastL) {
            for (int x = tid; x < 128 * SLOTS; x += 256) {
                int r = x >> 4, sl = x & (SLOTS - 1);
                unsigned k = rm[x];
                if (k != SENTINEL)
                    atomicMin(&g_rowmin[(size_t)(rowbase + r) * NG + gl_lo + sl], k);
            }
        }
        if (fastN) {
            for (int x = tid; x < 128 * SLOTS; x += 256) {
                int cc = x >> 4, sl = x & (SLOTS - 1);
                unsigned k = cm[x];
                if (k != SENTINEL)
                    atomicMin(&g_colmin[(size_t)(gn_lo + sl) * EL + jbase + cc], k);
            }
        }
    }
}

// ---------------- small kernels (R10, frozen) --------------------------------
__global__ void hist_kernel(const int* __restrict__ nbatch,
                            const int* __restrict__ lbatch) {
    int idx = blockIdx.x * blockDim.x + threadIdx.x;
    if (idx < EN) atomicAdd(&g_cntn[nbatch[idx]], 1);
    else if (idx < EN + EL) atomicAdd(&g_cntl[lbatch[idx - EN]], 1);
}

__global__ void row_sum_kernel(const int* __restrict__ nbatch) {
    int gl = blockIdx.x;
    int base = blockIdx.y * 512;
    int t = threadIdx.x;
    #pragma unroll
    for (int it = 0; it < 2; ++it) {
        int i = base + it * 256 + t;
        unsigned k = g_rowmin[(size_t)i * NG + gl];
        float val = 0.f;
        if (k != SENTINEL) val = -sqrtf(fmaxf(g_na[i] + decf(k), 0.f));
        int gn = nbatch[i];
        int gn0 = __shfl_sync(0xffffffffu, gn, 0);
        if (__all_sync(0xffffffffu, gn == gn0)) {
            #pragma unroll
            for (int o = 16; o > 0; o >>= 1) val += __shfl_down_sync(0xffffffffu, val, o);
            if ((t & 31) == 0) atomicAdd(&g_sumn[gn0 * NG + gl], val);
        } else {
            atomicAdd(&g_sumn[gn * NG + gl], val);
        }
    }
}

__global__ void col_sum_kernel(const int* __restrict__ lbatch) {
    int gn = blockIdx.x;
    int base = blockIdx.y * 512;
    int t = threadIdx.x;
    #pragma unroll
    for (int it = 0; it < 2; ++it) {
        int j = base + it * 256 + t;
        unsigned k = g_colmin[(size_t)gn * EL + j];
        float val = 0.f;
        if (k != SENTINEL) val = -sqrtf(fmaxf(g_nb[j] + decf(k), 0.f));
        int gl = lbatch[j];
        int gl0 = __shfl_sync(0xffffffffu, gl, 0);
        if (__all_sync(0xffffffffu, gl == gl0)) {
            #pragma unroll
            for (int o = 16; o > 0; o >>= 1) val += __shfl_down_sync(0xffffffffu, val, o);
            if ((t & 31) == 0) atomicAdd(&g_suml[gn * NG + gl0], val);
        } else {
            atomicAdd(&g_suml[gn * NG + gl], val);
        }
    }
}

__global__ void combine_kernel(float* __restrict__ out) {
    int idx = blockIdx.x * blockDim.x + threadIdx.x;
    if (idx < NG * NG) {
        int gn = idx >> 6, gl = idx & (NG - 1);
        float on = g_sumn[idx] / (float)max(g_cntn[gn], 1);
        float ol = g_suml[idx] / (float)max(g_cntl[gl], 1);
        out[idx] = 0.5f * (on + ol);
    }
}

// ---------------- launch -------------------------------------------------------
extern "C" void kernel_launch(void* const* d_in, const int* in_sizes, int n_in,
                              void* d_out, int out_size) {
    const float* h           = (const float*)d_in[0];
    const int*   node_edge   = (const int*)d_in[1];
    const int*   node_batch  = (const int*)d_in[2];
    const int*   label_edge  = (const int*)d_in[3];
    const int*   label_batch = (const int*)d_in[4];
    float* out = (float*)d_out;

    cudaFuncSetAttribute(gemm_fullk_kernel,
                         cudaFuncAttributeMaxDynamicSharedMemorySize, SMEM_TC);

    init_mins_kernel<<<(EN * NG + 255) / 256, 256>>>();
    build_ef_kernel<<<EN, 256>>>(h, node_edge, 0);
    build_ef_kernel<<<EL, 256>>>(h, label_edge, 1);
    gemm_fullk_kernel<<<256, 256, SMEM_TC>>>(node_batch, label_batch);
    hist_kernel<<<(EN + EL + 255) / 256, 256>>>(node_batch, label_batch);
    row_sum_kernel<<<dim3(NG, 16), 256>>>(node_batch);
    col_sum_kernel<<<dim3(NG, 16), 256>>>(label_batch);
    combine_kernel<<<(NG * NG + 255) / 256, 256>>>(out);
}

// round 13
// speedup vs baseline: 2.0131x; 2.0131x over previous
#include <cuda_runtime.h>
#include <cuda_bf16.h>
#include <cstdint>

#define EN 8192
#define EL 8192
#define DD 256
#define NG 64
#define SLOTS 16

// ---------------- scratch (device globals) ----------------------------------
__device__ __align__(128) __nv_bfloat16 g_efn_bf[EN * DD];
__device__ __align__(128) __nv_bfloat16 g_efl_bf[EL * DD];
__device__ __align__(128) float    g_na[EN];
__device__ __align__(128) float    g_nb[EL];
__device__ __align__(128) unsigned g_rowmin[EN * NG];   // [i][gl]
__device__ __align__(128) unsigned g_colmin[NG * EL];   // [gn][j]
__device__ __align__(128) float    g_sumn[NG * NG];
__device__ __align__(128) float    g_suml[NG * NG];
__device__ __align__(128) int      g_cntn[NG];
__device__ __align__(128) int      g_cntl[NG];

__device__ __forceinline__ unsigned encf(float f) {
    unsigned u = __float_as_uint(f);
    return (u & 0x80000000u) ? ~u : (u | 0x80000000u);
}
__device__ __forceinline__ float decf(unsigned k) {
    unsigned u = (k & 0x80000000u) ? (k & 0x7FFFFFFFu) : ~k;
    return __uint_as_float(u);
}

#define SENTINEL 0xFFFFFFFFu
#define INF_F __int_as_float(0x7f800000)

// ---------------- kernel 0 ---------------------------------------------------
__global__ void init_mins_kernel() {
    int i = blockIdx.x * blockDim.x + threadIdx.x;
    if (i < EN * NG) {
        g_rowmin[i] = SENTINEL;
        g_colmin[i] = SENTINEL;
    }
    if (i < NG * NG) { g_sumn[i] = 0.f; g_suml[i] = 0.f; }
    if (i < NG)      { g_cntn[i] = 0;   g_cntl[i] = 0; }
}

// ---------------- kernel 1 ---------------------------------------------------
__global__ void build_ef_kernel(const float* __restrict__ h,
                                const int* __restrict__ edge,
                                int which) {
    __nv_bfloat16* ef = which ? g_efl_bf : g_efn_bf;
    float* nrm        = which ? g_nb     : g_na;
    int e = blockIdx.x;
    int t = threadIdx.x;
    int i0 = edge[e];
    int i1 = edge[EN + e];
    float v = 0.5f * (h[(size_t)i0 * DD + t] + h[(size_t)i1 * DD + t]);
    ef[(size_t)e * DD + t] = __float2bfloat16_rn(v);
    float s = v * v;
    #pragma unroll
    for (int o = 16; o > 0; o >>= 1) s += __shfl_down_sync(0xffffffffu, s, o);
    __shared__ float ws[8];
    if ((t & 31) == 0) ws[t >> 5] = s;
    __syncthreads();
    if (t < 8) {
        float x = ws[t];
        #pragma unroll
        for (int o = 4; o > 0; o >>= 1) x += __shfl_down_sync(0xffu, x, o);
        if (t == 0) nrm[e] = x;
    }
}

// ---------------- PTX helpers -------------------------------------------------
__device__ __forceinline__ void cp16(uint32_t dst, const void* src) {
    asm volatile("cp.async.cg.shared.global [%0], [%1], 16;" :: "r"(dst), "l"(src));
}
__device__ __forceinline__ void cp_commit() { asm volatile("cp.async.commit_group;"); }
__device__ __forceinline__ void cp_wait0()  { asm volatile("cp.async.wait_group 0;"); }
__device__ __forceinline__ void ldmx4(uint32_t* r, uint32_t addr) {
    asm volatile("ldmatrix.sync.aligned.m8n8.x4.shared.b16 {%0,%1,%2,%3}, [%4];"
                 : "=r"(r[0]), "=r"(r[1]), "=r"(r[2]), "=r"(r[3]) : "r"(addr));
}
__device__ __forceinline__ void mma16816(float* d, const uint32_t* a,
                                         uint32_t b0, uint32_t b1) {
    asm volatile("mma.sync.aligned.m16n8k16.row.col.f32.bf16.bf16.f32 "
                 "{%0,%1,%2,%3}, {%4,%5,%6,%7}, {%8,%9}, {%0,%1,%2,%3};"
                 : "+f"(d[0]), "+f"(d[1]), "+f"(d[2]), "+f"(d[3])
                 : "r"(a[0]), "r"(a[1]), "r"(a[2]), "r"(a[3]), "r"(b0), "r"(b1));
}

// ---------------- kernel 2: bf16 MMA GEMM, BK=64, 2 CTAs/SM ------------------
// Same structure as the R10 passing kernel; only the K-stage width changed
// (32 -> 64): 4 barriers per tile instead of 8, 2x unfenced LDSM/HMMA window.
#define LDA 72                          // 64 + 8 pad (bf16 elems); row = 144 B
#define HALF_B  (128 * LDA * 2)         // 18432 B (one operand, one stage)
#define STAGE_B (2 * HALF_B)            // 36864 B (A+B, one stage)
#define SMEM_GM (2 * STAGE_B + 1024 + 1024)   // stages + gnc/glc + align pad

__global__ void __launch_bounds__(256, 2)
gemm_bf16_min_kernel(const int* __restrict__ nbatch,
                     const int* __restrict__ lbatch) {
    extern __shared__ char dsm_raw[];
    const uint32_t sraw = (uint32_t)__cvta_generic_to_shared(dsm_raw);
    const uint32_t s0 = (sraw + 1023u) & ~1023u;
    char* p0 = dsm_raw + (s0 - sraw);

    int* gnc = (int*)(p0 + 2 * STAGE_B);        // [128]
    int* glc = (int*)(p0 + 2 * STAGE_B + 512);  // [128]

    const int tid   = threadIdx.x;
    const int tileI = blockIdx.y * 128;
    const int tileJ = blockIdx.x * 128;
    const int wid  = tid >> 5;
    const int lane = tid & 31;
    const int wr = wid & 1;
    const int wc = wid >> 1;
    const int wrBase = wr * 64;
    const int wcBase = wc * 32;

    const uint32_t smemBase = s0;

    const int aRow = (lane & 7) + ((lane >> 3) & 1) * 8;
    const int aK   = (lane >> 4) * 8;
    const int bRow = (lane & 7) + (lane >> 4) * 8;
    const int bK   = ((lane >> 3) & 1) * 8;

    if (tid < 128) {
        gnc[tid] = nbatch[tileI + tid];
        glc[tid] = lbatch[tileJ + tid];
    }

    float c[4][4][4];
    #pragma unroll
    for (int mi = 0; mi < 4; mi++)
        #pragma unroll
        for (int ni = 0; ni < 4; ni++)
            #pragma unroll
            for (int q = 0; q < 4; q++) c[mi][ni][q] = 0.f;

    // loader: per stage, each thread moves 4 chunks of 16B for A and 4 for B.
    // id = it*256 + tid; r = id>>3 (8 chunks/row of 64 bf16), kq = (id&7)*8.
    // prologue: stage 0
    {
        uint32_t st = smemBase;
        #pragma unroll
        for (int it = 0; it < 4; ++it) {
            int id = it * 256 + tid;
            int r = id >> 3, kq = (id & 7) * 8;
            uint32_t d = (uint32_t)(r * LDA + kq) * 2;
            cp16(st + d,          g_efn_bf + (size_t)(tileI + r) * DD + kq);
            cp16(st + HALF_B + d, g_efl_bf + (size_t)(tileJ + r) * DD + kq);
        }
        cp_commit();
    }

    const int NS = DD / 64;  // 4 stages
    for (int s = 0; s < NS; ++s) {
        cp_wait0();
        __syncthreads();
        if (s + 1 < NS) {
            uint32_t st = smemBase + ((s + 1) & 1) * STAGE_B;
            int ko = (s + 1) * 64;
            #pragma unroll
            for (int it = 0; it < 4; ++it) {
                int id = it * 256 + tid;
                int r = id >> 3, kq = (id & 7) * 8;
                uint32_t d = (uint32_t)(r * LDA + kq) * 2;
                cp16(st + d,          g_efn_bf + (size_t)(tileI + r) * DD + ko + kq);
                cp16(st + HALF_B + d, g_efl_bf + (size_t)(tileJ + r) * DD + ko + kq);
            }
            cp_commit();
        }
        uint32_t sA = smemBase + (s & 1) * STAGE_B;
        uint32_t sB = sA + HALF_B;
        #pragma unroll
        for (int kb = 0; kb < 64; kb += 16) {
            uint32_t a[4][4];
            #pragma unroll
            for (int mi = 0; mi < 4; mi++)
                ldmx4(a[mi], sA + (uint32_t)((wrBase + mi * 16 + aRow) * LDA + kb + aK) * 2);
            uint32_t b[2][4];
            #pragma unroll
            for (int nq = 0; nq < 2; nq++)
                ldmx4(b[nq], sB + (uint32_t)((wcBase + nq * 16 + bRow) * LDA + kb + bK) * 2);
            #pragma unroll
            for (int mi = 0; mi < 4; mi++) {
                #pragma unroll
                for (int nq = 0; nq < 2; nq++) {
                    mma16816(c[mi][nq * 2 + 0], a[mi], b[nq][0], b[nq][1]);
                    mma16816(c[mi][nq * 2 + 1], a[mi], b[nq][2], b[nq][3]);
                }
            }
        }
    }
    __syncthreads();

    // -------- epilogue: overlay staging on operand smem, group-min reduce ---
    unsigned* stag = (unsigned*)p0;
    for (int x = tid; x < 128 * SLOTS * 2; x += 256) stag[x] = SENTINEL;
    __syncthreads();
    unsigned (*rm)[SLOTS] = (unsigned(*)[SLOTS])stag;
    unsigned (*cm)[SLOTS] = (unsigned(*)[SLOTS])(stag + 128 * SLOTS);

    const int gl_lo = glc[0], gl_hi = glc[127];
    const int gn_lo = gnc[0], gn_hi = gnc[127];
    const bool fastL = (gl_hi - gl_lo) < SLOTS;
    const bool fastN = (gn_hi - gn_lo) < SLOTS;

    const int g  = lane >> 2;
    const int t2 = (lane & 3) * 2;

    int   lrows[8], grows[8], lcols[8], gcols[8];
    float nav[8], nbv[8];
    #pragma unroll
    for (int m = 0; m < 8; m++) {
        lrows[m] = wrBase + (m >> 1) * 16 + g + (m & 1) * 8;
        grows[m] = gnc[lrows[m]];
        nav[m]   = g_na[tileI + lrows[m]];
    }
    #pragma unroll
    for (int n = 0; n < 8; n++) {
        lcols[n] = wcBase + (n >> 1) * 8 + t2 + (n & 1);
        gcols[n] = glc[lcols[n]];
        nbv[n]   = g_nb[tileJ + lcols[n]];
    }

    // row-side
    #pragma unroll
    for (int m = 0; m < 8; m++) {
        const int mi = m >> 1, hh = m & 1;
        float rbest = INF_F;
        int curgl = -1;
        #pragma unroll
        for (int n = 0; n < 8; n++) {
            const int ni = n >> 1, u = n & 1;
            float rv = fmaf(-2.f, c[mi][ni][hh * 2 + u], nbv[n]);
            int gg = gcols[n];
            if (gg != curgl) {
                if (curgl >= 0) {
                    unsigned k = encf(rbest);
                    if (fastL) atomicMin(&rm[lrows[m]][curgl - gl_lo], k);
                    else       atomicMin(&g_rowmin[(size_t)(tileI + lrows[m]) * NG + curgl], k);
                }
                curgl = gg; rbest = rv;
            } else {
                rbest = fminf(rbest, rv);
            }
        }
        unsigned k = encf(rbest);
        if (fastL) atomicMin(&rm[lrows[m]][curgl - gl_lo], k);
        else       atomicMin(&g_rowmin[(size_t)(tileI + lrows[m]) * NG + curgl], k);
    }

    // col-side
    {
        float cb[8];
        #pragma unroll
        for (int n = 0; n < 8; n++) cb[n] = INF_F;
        int curgn = -1;
        #pragma unroll
        for (int m = 0; m < 8; m++) {
            const int mi = m >> 1, hh = m & 1;
            int gi = grows[m];
            if (gi != curgn) {
                if (curgn >= 0) {
                    #pragma unroll
                    for (int n = 0; n < 8; n++) {
                        unsigned k = encf(cb[n]);
                        if (fastN) atomicMin(&cm[lcols[n]][curgn - gn_lo], k);
                        else       atomicMin(&g_colmin[(size_t)curgn * EL + tileJ + lcols[n]], k);
                        cb[n] = INF_F;
                    }
                }
                curgn = gi;
            }
            #pragma unroll
            for (int n = 0; n < 8; n++) {
                const int ni = n >> 1, u = n & 1;
                cb[n] = fminf(cb[n], fmaf(-2.f, c[mi][ni][hh * 2 + u], nav[m]));
            }
        }
        #pragma unroll
        for (int n = 0; n < 8; n++) {
            unsigned k = encf(cb[n]);
            if (fastN) atomicMin(&cm[lcols[n]][curgn - gn_lo], k);
            else       atomicMin(&g_colmin[(size_t)curgn * EL + tileJ + lcols[n]], k);
        }
    }
    __syncthreads();

    // flush staging (R7/R10-proven pattern)
    if (fastL) {
        for (int x = tid; x < 128 * SLOTS; x += 256) {
            int r = x >> 4, sl = x & (SLOTS - 1);
            unsigned k = rm[r][sl];
            if (k != SENTINEL)
                atomicMin(&g_rowmin[(size_t)(tileI + r) * NG + gl_lo + sl], k);
        }
    }
    if (fastN) {
        for (int x = tid; x < 128 * SLOTS; x += 256) {
            int cc = x >> 4, sl = x & (SLOTS - 1);
            unsigned k = cm[cc][sl];
            if (k != SENTINEL)
                atomicMin(&g_colmin[(size_t)(gn_lo + sl) * EL + tileJ + cc], k);
        }
    }
}

// ---------------- small kernels (R10, frozen) --------------------------------
__global__ void hist_kernel(const int* __restrict__ nbatch,
                            const int* __restrict__ lbatch) {
    int idx = blockIdx.x * blockDim.x + threadIdx.x;
    if (idx < EN) atomicAdd(&g_cntn[nbatch[idx]], 1);
    else if (idx < EN + EL) atomicAdd(&g_cntl[lbatch[idx - EN]], 1);
}

__global__ void row_sum_kernel(const int* __restrict__ nbatch) {
    int gl = blockIdx.x;
    int base = blockIdx.y * 512;
    int t = threadIdx.x;
    #pragma unroll
    for (int it = 0; it < 2; ++it) {
        int i = base + it * 256 + t;
        unsigned k = g_rowmin[(size_t)i * NG + gl];
        float val = 0.f;
        if (k != SENTINEL) val = -sqrtf(fmaxf(g_na[i] + decf(k), 0.f));
        int gn = nbatch[i];
        int gn0 = __shfl_sync(0xffffffffu, gn, 0);
        if (__all_sync(0xffffffffu, gn == gn0)) {
            #pragma unroll
            for (int o = 16; o > 0; o >>= 1) val += __shfl_down_sync(0xffffffffu, val, o);
            if ((t & 31) == 0) atomicAdd(&g_sumn[gn0 * NG + gl], val);
        } else {
            atomicAdd(&g_sumn[gn * NG + gl], val);
        }
    }
}

__global__ void col_sum_kernel(const int* __restrict__ lbatch) {
    int gn = blockIdx.x;
    int base = blockIdx.y * 512;
    int t = threadIdx.x;
    #pragma unroll
    for (int it = 0; it < 2; ++it) {
        int j = base + it * 256 + t;
        unsigned k = g_colmin[(size_t)gn * EL + j];
        float val = 0.f;
        if (k != SENTINEL) val = -sqrtf(fmaxf(g_nb[j] + decf(k), 0.f));
        int gl = lbatch[j];
        int gl0 = __shfl_sync(0xffffffffu, gl, 0);
        if (__all_sync(0xffffffffu, gl == gl0)) {
            #pragma unroll
            for (int o = 16; o > 0; o >>= 1) val += __shfl_down_sync(0xffffffffu, val, o);
            if ((t & 31) == 0) atomicAdd(&g_suml[gn * NG + gl0], val);
        } else {
            atomicAdd(&g_suml[gn * NG + gl], val);
        }
    }
}

__global__ void combine_kernel(float* __restrict__ out) {
    int idx = blockIdx.x * blockDim.x + threadIdx.x;
    if (idx < NG * NG) {
        int gn = idx >> 6, gl = idx & (NG - 1);
        float on = g_sumn[idx] / (float)max(g_cntn[gn], 1);
        float ol = g_suml[idx] / (float)max(g_cntl[gl], 1);
        out[idx] = 0.5f * (on + ol);
    }
}

// ---------------- launch -------------------------------------------------------
extern "C" void kernel_launch(void* const* d_in, const int* in_sizes, int n_in,
                              void* d_out, int out_size) {
    const float* h           = (const float*)d_in[0];
    const int*   node_edge   = (const int*)d_in[1];
    const int*   node_batch  = (const int*)d_in[2];
    const int*   label_edge  = (const int*)d_in[3];
    const int*   label_batch = (const int*)d_in[4];
    float* out = (float*)d_out;

    cudaFuncSetAttribute(gemm_bf16_min_kernel,
                         cudaFuncAttributeMaxDynamicSharedMemorySize, SMEM_GM);

    init_mins_kernel<<<(EN * NG + 255) / 256, 256>>>();
    build_ef_kernel<<<EN, 256>>>(h, node_edge, 0);
    build_ef_kernel<<<EL, 256>>>(h, label_edge, 1);
    gemm_bf16_min_kernel<<<dim3(EL / 128, EN / 128), 256, SMEM_GM>>>(node_batch, label_batch);
    hist_kernel<<<(EN + EL + 255) / 256, 256>>>(node_batch, label_batch);
    row_sum_kernel<<<dim3(NG, 16), 256>>>(node_batch);
    col_sum_kernel<<<dim3(NG, 16), 256>>>(label_batch);
    combine_kernel<<<(NG * NG + 255) / 256, 256>>>(out);
}

// round 14
// speedup vs baseline: 2.0283x; 1.0076x over previous
#include <cuda_runtime.h>
#include <cuda_bf16.h>
#include <cstdint>

#define EN 8192
#define EL 8192
#define DD 256
#define NG 64
#define SLOTS 16

// ---------------- scratch (device globals) ----------------------------------
__device__ __align__(128) __nv_bfloat16 g_efn_bf[EN * DD];
__device__ __align__(128) __nv_bfloat16 g_efl_bf[EL * DD];
__device__ __align__(128) float    g_na[EN];
__device__ __align__(128) float    g_nb[EL];
__device__ __align__(128) unsigned g_rowmin[EN * NG];   // [i][gl]
__device__ __align__(128) unsigned g_colmin[NG * EL];   // [gn][j]
__device__ __align__(128) float    g_sumn[NG * NG];
__device__ __align__(128) float    g_suml[NG * NG];
__device__ __align__(128) int      g_cntn[NG];
__device__ __align__(128) int      g_cntl[NG];

__device__ __forceinline__ unsigned encf(float f) {
    unsigned u = __float_as_uint(f);
    return (u & 0x80000000u) ? ~u : (u | 0x80000000u);
}
__device__ __forceinline__ float decf(unsigned k) {
    unsigned u = (k & 0x80000000u) ? (k & 0x7FFFFFFFu) : ~k;
    return __uint_as_float(u);
}

#define SENTINEL 0xFFFFFFFFu
#define INF_F __int_as_float(0x7f800000)

// ---------------- kernel 0 ---------------------------------------------------
__global__ void init_mins_kernel() {
    int i = blockIdx.x * blockDim.x + threadIdx.x;
    if (i < EN * NG) {
        g_rowmin[i] = SENTINEL;
        g_colmin[i] = SENTINEL;
    }
    if (i < NG * NG) { g_sumn[i] = 0.f; g_suml[i] = 0.f; }
    if (i < NG)      { g_cntn[i] = 0;   g_cntl[i] = 0; }
}

// ---------------- kernel 1 ---------------------------------------------------
__global__ void build_ef_kernel(const float* __restrict__ h,
                                const int* __restrict__ edge,
                                int which) {
    __nv_bfloat16* ef = which ? g_efl_bf : g_efn_bf;
    float* nrm        = which ? g_nb     : g_na;
    int e = blockIdx.x;
    int t = threadIdx.x;
    int i0 = edge[e];
    int i1 = edge[EN + e];
    float v = 0.5f * (h[(size_t)i0 * DD + t] + h[(size_t)i1 * DD + t]);
    ef[(size_t)e * DD + t] = __float2bfloat16_rn(v);
    float s = v * v;
    #pragma unroll
    for (int o = 16; o > 0; o >>= 1) s += __shfl_down_sync(0xffffffffu, s, o);
    __shared__ float ws[8];
    if ((t & 31) == 0) ws[t >> 5] = s;
    __syncthreads();
    if (t < 8) {
        float x = ws[t];
        #pragma unroll
        for (int o = 4; o > 0; o >>= 1) x += __shfl_down_sync(0xffu, x, o);
        if (t == 0) nrm[e] = x;
    }
}

// ---------------- PTX helpers -------------------------------------------------
__device__ __forceinline__ void cp16(uint32_t dst, const void* src) {
    asm volatile("cp.async.cg.shared.global [%0], [%1], 16;" :: "r"(dst), "l"(src));
}
__device__ __forceinline__ void cp_commit() { asm volatile("cp.async.commit_group;"); }
__device__ __forceinline__ void cp_wait0()  { asm volatile("cp.async.wait_group 0;"); }
__device__ __forceinline__ void cp_wait1()  { asm volatile("cp.async.wait_group 1;"); }
__device__ __forceinline__ void ldmx4(uint32_t* r, uint32_t addr) {
    asm volatile("ldmatrix.sync.aligned.m8n8.x4.shared.b16 {%0,%1,%2,%3}, [%4];"
                 : "=r"(r[0]), "=r"(r[1]), "=r"(r[2]), "=r"(r[3]) : "r"(addr));
}
__device__ __forceinline__ void mma16816(float* d, const uint32_t* a,
                                         uint32_t b0, uint32_t b1) {
    asm volatile("mma.sync.aligned.m16n8k16.row.col.f32.bf16.bf16.f32 "
                 "{%0,%1,%2,%3}, {%4,%5,%6,%7}, {%8,%9}, {%0,%1,%2,%3};"
                 : "+f"(d[0]), "+f"(d[1]), "+f"(d[2]), "+f"(d[3])
                 : "r"(a[0]), "r"(a[1]), "r"(a[2]), "r"(a[3]), "r"(b0), "r"(b1));
}

// ---------------- kernel 2: bf16 MMA GEMM, BK=64, 3-stage pipeline ----------
// R13 structure with one change: 2 -> 3 cp.async stages; loads run two stages
// ahead so the per-stage wait is (almost) never binding.
#define LDA 72                          // 64 + 8 pad (bf16 elems); row = 144 B
#define HALF_B  (128 * LDA * 2)         // 18432 B
#define STAGE_B (2 * HALF_B)            // 36864 B
#define NSTAGES 3
#define SMEM_GM (NSTAGES * STAGE_B + 1024 + 1024)

__global__ void __launch_bounds__(256, 2)
gemm_bf16_min_kernel(const int* __restrict__ nbatch,
                     const int* __restrict__ lbatch) {
    extern __shared__ char dsm_raw[];
    const uint32_t sraw = (uint32_t)__cvta_generic_to_shared(dsm_raw);
    const uint32_t s0 = (sraw + 1023u) & ~1023u;
    char* p0 = dsm_raw + (s0 - sraw);

    int* gnc = (int*)(p0 + NSTAGES * STAGE_B);        // [128]
    int* glc = (int*)(p0 + NSTAGES * STAGE_B + 512);  // [128]

    const int tid   = threadIdx.x;
    const int tileI = blockIdx.y * 128;
    const int tileJ = blockIdx.x * 128;
    const int wid  = tid >> 5;
    const int lane = tid & 31;
    const int wr = wid & 1;
    const int wc = wid >> 1;
    const int wrBase = wr * 64;
    const int wcBase = wc * 32;

    const uint32_t smemBase = s0;

    const int aRow = (lane & 7) + ((lane >> 3) & 1) * 8;
    const int aK   = (lane >> 4) * 8;
    const int bRow = (lane & 7) + (lane >> 4) * 8;
    const int bK   = ((lane >> 3) & 1) * 8;

    if (tid < 128) {
        gnc[tid] = nbatch[tileI + tid];
        glc[tid] = lbatch[tileJ + tid];
    }

    float c[4][4][4];
    #pragma unroll
    for (int mi = 0; mi < 4; mi++)
        #pragma unroll
        for (int ni = 0; ni < 4; ni++)
            #pragma unroll
            for (int q = 0; q < 4; q++) c[mi][ni][q] = 0.f;

    // loader for one BK=64 stage: 4 chunks of 16B for A and 4 for B per thread
    // prologue: stages 0 and 1
    #pragma unroll
    for (int ps = 0; ps < 2; ++ps) {
        uint32_t st = smemBase + ps * STAGE_B;
        int ko = ps * 64;
        #pragma unroll
        for (int it = 0; it < 4; ++it) {
            int id = it * 256 + tid;
            int r = id >> 3, kq = (id & 7) * 8;
            uint32_t d = (uint32_t)(r * LDA + kq) * 2;
            cp16(st + d,          g_efn_bf + (size_t)(tileI + r) * DD + ko + kq);
            cp16(st + HALF_B + d, g_efl_bf + (size_t)(tileJ + r) * DD + ko + kq);
        }
        cp_commit();
    }

    const int NS = DD / 64;  // 4 stages of work
    for (int s = 0; s < NS; ++s) {
        if (s < NS - 1) cp_wait1(); else cp_wait0();
        __syncthreads();
        if (s + 2 < NS) {
            int bs = (s + 2) % NSTAGES;
            uint32_t st = smemBase + bs * STAGE_B;
            int ko = (s + 2) * 64;
            #pragma unroll
            for (int it = 0; it < 4; ++it) {
                int id = it * 256 + tid;
                int r = id >> 3, kq = (id & 7) * 8;
                uint32_t d = (uint32_t)(r * LDA + kq) * 2;
                cp16(st + d,          g_efn_bf + (size_t)(tileI + r) * DD + ko + kq);
                cp16(st + HALF_B + d, g_efl_bf + (size_t)(tileJ + r) * DD + ko + kq);
            }
            cp_commit();
        }
        uint32_t sA = smemBase + (s % NSTAGES) * STAGE_B;
        uint32_t sB = sA + HALF_B;
        #pragma unroll
        for (int kb = 0; kb < 64; kb += 16) {
            uint32_t a[4][4];
            #pragma unroll
            for (int mi = 0; mi < 4; mi++)
                ldmx4(a[mi], sA + (uint32_t)((wrBase + mi * 16 + aRow) * LDA + kb + aK) * 2);
            uint32_t b[2][4];
            #pragma unroll
            for (int nq = 0; nq < 2; nq++)
                ldmx4(b[nq], sB + (uint32_t)((wcBase + nq * 16 + bRow) * LDA + kb + bK) * 2);
            #pragma unroll
            for (int mi = 0; mi < 4; mi++) {
                #pragma unroll
                for (int nq = 0; nq < 2; nq++) {
                    mma16816(c[mi][nq * 2 + 0], a[mi], b[nq][0], b[nq][1]);
                    mma16816(c[mi][nq * 2 + 1], a[mi], b[nq][2], b[nq][3]);
                }
            }
        }
    }
    __syncthreads();

    // -------- epilogue: overlay staging on operand smem, group-min reduce ---
    unsigned* stag = (unsigned*)p0;
    for (int x = tid; x < 128 * SLOTS * 2; x += 256) stag[x] = SENTINEL;
    __syncthreads();
    unsigned (*rm)[SLOTS] = (unsigned(*)[SLOTS])stag;
    unsigned (*cm)[SLOTS] = (unsigned(*)[SLOTS])(stag + 128 * SLOTS);

    const int gl_lo = glc[0], gl_hi = glc[127];
    const int gn_lo = gnc[0], gn_hi = gnc[127];
    const bool fastL = (gl_hi - gl_lo) < SLOTS;
    const bool fastN = (gn_hi - gn_lo) < SLOTS;

    const int g  = lane >> 2;
    const int t2 = (lane & 3) * 2;

    int   lrows[8], grows[8], lcols[8], gcols[8];
    float nav[8], nbv[8];
    #pragma unroll
    for (int m = 0; m < 8; m++) {
        lrows[m] = wrBase + (m >> 1) * 16 + g + (m & 1) * 8;
        grows[m] = gnc[lrows[m]];
        nav[m]   = g_na[tileI + lrows[m]];
    }
    #pragma unroll
    for (int n = 0; n < 8; n++) {
        lcols[n] = wcBase + (n >> 1) * 8 + t2 + (n & 1);
        gcols[n] = glc[lcols[n]];
        nbv[n]   = g_nb[tileJ + lcols[n]];
    }

    // row-side
    #pragma unroll
    for (int m = 0; m < 8; m++) {
        const int mi = m >> 1, hh = m & 1;
        float rbest = INF_F;
        int curgl = -1;
        #pragma unroll
        for (int n = 0; n < 8; n++) {
            const int ni = n >> 1, u = n & 1;
            float rv = fmaf(-2.f, c[mi][ni][hh * 2 + u], nbv[n]);
            int gg = gcols[n];
            if (gg != curgl) {
                if (curgl >= 0) {
                    unsigned k = encf(rbest);
                    if (fastL) atomicMin(&rm[lrows[m]][curgl - gl_lo], k);
                    else       atomicMin(&g_rowmin[(size_t)(tileI + lrows[m]) * NG + curgl], k);
                }
                curgl = gg; rbest = rv;
            } else {
                rbest = fminf(rbest, rv);
            }
        }
        unsigned k = encf(rbest);
        if (fastL) atomicMin(&rm[lrows[m]][curgl - gl_lo], k);
        else       atomicMin(&g_rowmin[(size_t)(tileI + lrows[m]) * NG + curgl], k);
    }

    // col-side
    {
        float cb[8];
        #pragma unroll
        for (int n = 0; n < 8; n++) cb[n] = INF_F;
        int curgn = -1;
        #pragma unroll
        for (int m = 0; m < 8; m++) {
            const int mi = m >> 1, hh = m & 1;
            int gi = grows[m];
            if (gi != curgn) {
                if (curgn >= 0) {
                    #pragma unroll
                    for (int n = 0; n < 8; n++) {
                        unsigned k = encf(cb[n]);
                        if (fastN) atomicMin(&cm[lcols[n]][curgn - gn_lo], k);
                        else       atomicMin(&g_colmin[(size_t)curgn * EL + tileJ + lcols[n]], k);
                        cb[n] = INF_F;
                    }
                }
                curgn = gi;
            }
            #pragma unroll
            for (int n = 0; n < 8; n++) {
                const int ni = n >> 1, u = n & 1;
                cb[n] = fminf(cb[n], fmaf(-2.f, c[mi][ni][hh * 2 + u], nav[m]));
            }
        }
        #pragma unroll
        for (int n = 0; n < 8; n++) {
            unsigned k = encf(cb[n]);
            if (fastN) atomicMin(&cm[lcols[n]][curgn - gn_lo], k);
            else       atomicMin(&g_colmin[(size_t)curgn * EL + tileJ + lcols[n]], k);
        }
    }
    __syncthreads();

    // flush staging (R7/R10-proven pattern)
    if (fastL) {
        for (int x = tid; x < 128 * SLOTS; x += 256) {
            int r = x >> 4, sl = x & (SLOTS - 1);
            unsigned k = rm[r][sl];
            if (k != SENTINEL)
                atomicMin(&g_rowmin[(size_t)(tileI + r) * NG + gl_lo + sl], k);
        }
    }
    if (fastN) {
        for (int x = tid; x < 128 * SLOTS; x += 256) {
            int cc = x >> 4, sl = x & (SLOTS - 1);
            unsigned k = cm[cc][sl];
            if (k != SENTINEL)
                atomicMin(&g_colmin[(size_t)(gn_lo + sl) * EL + tileJ + cc], k);
        }
    }
}

// ---------------- small kernels (R10, frozen) --------------------------------
__global__ void hist_kernel(const int* __restrict__ nbatch,
                            const int* __restrict__ lbatch) {
    int idx = blockIdx.x * blockDim.x + threadIdx.x;
    if (idx < EN) atomicAdd(&g_cntn[nbatch[idx]], 1);
    else if (idx < EN + EL) atomicAdd(&g_cntl[lbatch[idx - EN]], 1);
}

__global__ void row_sum_kernel(const int* __restrict__ nbatch) {
    int gl = blockIdx.x;
    int base = blockIdx.y * 512;
    int t = threadIdx.x;
    #pragma unroll
    for (int it = 0; it < 2; ++it) {
        int i = base + it * 256 + t;
        unsigned k = g_rowmin[(size_t)i * NG + gl];
        float val = 0.f;
        if (k != SENTINEL) val = -sqrtf(fmaxf(g_na[i] + decf(k), 0.f));
        int gn = nbatch[i];
        int gn0 = __shfl_sync(0xffffffffu, gn, 0);
        if (__all_sync(0xffffffffu, gn == gn0)) {
            #pragma unroll
            for (int o = 16; o > 0; o >>= 1) val += __shfl_down_sync(0xffffffffu, val, o);
            if ((t & 31) == 0) atomicAdd(&g_sumn[gn0 * NG + gl], val);
        } else {
            atomicAdd(&g_sumn[gn * NG + gl], val);
        }
    }
}

__global__ void col_sum_kernel(const int* __restrict__ lbatch) {
    int gn = blockIdx.x;
    int base = blockIdx.y * 512;
    int t = threadIdx.x;
    #pragma unroll
    for (int it = 0; it < 2; ++it) {
        int j = base + it * 256 + t;
        unsigned k = g_colmin[(size_t)gn * EL + j];
        float val = 0.f;
        if (k != SENTINEL) val = -sqrtf(fmaxf(g_nb[j] + decf(k), 0.f));
        int gl = lbatch[j];
        int gl0 = __shfl_sync(0xffffffffu, gl, 0);
        if (__all_sync(0xffffffffu, gl == gl0)) {
            #pragma unroll
            for (int o = 16; o > 0; o >>= 1) val += __shfl_down_sync(0xffffffffu, val, o);
            if ((t & 31) == 0) atomicAdd(&g_suml[gn * NG + gl0], val);
        } else {
            atomicAdd(&g_suml[gn * NG + gl], val);
        }
    }
}

__global__ void combine_kernel(float* __restrict__ out) {
    int idx = blockIdx.x * blockDim.x + threadIdx.x;
    if (idx < NG * NG) {
        int gn = idx >> 6, gl = idx & (NG - 1);
        float on = g_sumn[idx] / (float)max(g_cntn[gn], 1);
        float ol = g_suml[idx] / (float)max(g_cntl[gl], 1);
        out[idx] = 0.5f * (on + ol);
    }
}

// ---------------- launch -------------------------------------------------------
extern "C" void kernel_launch(void* const* d_in, const int* in_sizes, int n_in,
                              void* d_out, int out_size) {
    const float* h           = (const float*)d_in[0];
    const int*   node_edge   = (const int*)d_in[1];
    const int*   node_batch  = (const int*)d_in[2];
    const int*   label_edge  = (const int*)d_in[3];
    const int*   label_batch = (const int*)d_in[4];
    float* out = (float*)d_out;

    cudaFuncSetAttribute(gemm_bf16_min_kernel,
                         cudaFuncAttributeMaxDynamicSharedMemorySize, SMEM_GM);

    init_mins_kernel<<<(EN * NG + 255) / 256, 256>>>();
    build_ef_kernel<<<EN, 256>>>(h, node_edge, 0);
    build_ef_kernel<<<EL, 256>>>(h, label_edge, 1);
    gemm_bf16_min_kernel<<<dim3(EL / 128, EN / 128), 256, SMEM_GM>>>(node_batch, label_batch);
    hist_kernel<<<(EN + EL + 255) / 256, 256>>>(node_batch, label_batch);
    row_sum_kernel<<<dim3(NG, 16), 256>>>(node_batch);
    col_sum_kernel<<<dim3(NG, 16), 256>>>(label_batch);
    combine_kernel<<<(NG * NG + 255) / 256, 256>>>(out);
}

// round 15
// speedup vs baseline: 2.1746x; 1.0721x over previous
#include <cuda_runtime.h>
#include <cuda_bf16.h>
#include <cstdint>

#define EN 8192
#define EL 8192
#define DD 256
#define NG 64
#define CSLOTS 8          // col-side staging slots (node-group span per 128 rows)
#define GRID_P 296        // 2 CTAs x 148 SMs, persistent
#define NTILES 4096       // 64 x 64 tiles of 128x128

// ---------------- scratch (device globals) ----------------------------------
__device__ __align__(128) __nv_bfloat16 g_efn_bf[EN * DD];
__device__ __align__(128) __nv_bfloat16 g_efl_bf[EL * DD];
__device__ __align__(128) float    g_na[EN];
__device__ __align__(128) float    g_nb[EL];
__device__ __align__(128) unsigned g_rowmin[EN * NG];   // [i][gl]
__device__ __align__(128) unsigned g_colmin[NG * EL];   // [gn][j]
__device__ __align__(128) float    g_sumn[NG * NG];
__device__ __align__(128) float    g_suml[NG * NG];
__device__ __align__(128) int      g_cntn[NG];
__device__ __align__(128) int      g_cntl[NG];

__device__ __forceinline__ unsigned encf(float f) {
    unsigned u = __float_as_uint(f);
    return (u & 0x80000000u) ? ~u : (u | 0x80000000u);
}
__device__ __forceinline__ float decf(unsigned k) {
    unsigned u = (k & 0x80000000u) ? (k & 0x7FFFFFFFu) : ~k;
    return __uint_as_float(u);
}

#define SENTINEL 0xFFFFFFFFu
#define INF_F __int_as_float(0x7f800000)

// ---------------- kernel 0 ---------------------------------------------------
__global__ void init_mins_kernel() {
    int i = blockIdx.x * blockDim.x + threadIdx.x;
    if (i < EN * NG) {
        g_rowmin[i] = SENTINEL;
        g_colmin[i] = SENTINEL;
    }
    if (i < NG * NG) { g_sumn[i] = 0.f; g_suml[i] = 0.f; }
    if (i < NG)      { g_cntn[i] = 0;   g_cntl[i] = 0; }
}

// ---------------- kernel 1 ---------------------------------------------------
__global__ void build_ef_kernel(const float* __restrict__ h,
                                const int* __restrict__ edge,
                                int which) {
    __nv_bfloat16* ef = which ? g_efl_bf : g_efn_bf;
    float* nrm        = which ? g_nb     : g_na;
    int e = blockIdx.x;
    int t = threadIdx.x;
    int i0 = edge[e];
    int i1 = edge[EN + e];
    float v = 0.5f * (h[(size_t)i0 * DD + t] + h[(size_t)i1 * DD + t]);
    ef[(size_t)e * DD + t] = __float2bfloat16_rn(v);
    float s = v * v;
    #pragma unroll
    for (int o = 16; o > 0; o >>= 1) s += __shfl_down_sync(0xffffffffu, s, o);
    __shared__ float ws[8];
    if ((t & 31) == 0) ws[t >> 5] = s;
    __syncthreads();
    if (t < 8) {
        float x = ws[t];
        #pragma unroll
        for (int o = 4; o > 0; o >>= 1) x += __shfl_down_sync(0xffu, x, o);
        if (t == 0) nrm[e] = x;
    }
}

// ---------------- PTX helpers -------------------------------------------------
__device__ __forceinline__ void cp16(uint32_t dst, const void* src) {
    asm volatile("cp.async.cg.shared.global [%0], [%1], 16;" :: "r"(dst), "l"(src));
}
__device__ __forceinline__ void cp_commit() { asm volatile("cp.async.commit_group;"); }
__device__ __forceinline__ void cp_wait0()  { asm volatile("cp.async.wait_group 0;"); }
__device__ __forceinline__ void ldmx4(uint32_t* r, uint32_t addr) {
    asm volatile("ldmatrix.sync.aligned.m8n8.x4.shared.b16 {%0,%1,%2,%3}, [%4];"
                 : "=r"(r[0]), "=r"(r[1]), "=r"(r[2]), "=r"(r[3]) : "r"(addr));
}
__device__ __forceinline__ void mma16816(float* d, const uint32_t* a,
                                         uint32_t b0, uint32_t b1) {
    asm volatile("mma.sync.aligned.m16n8k16.row.col.f32.bf16.bf16.f32 "
                 "{%0,%1,%2,%3}, {%4,%5,%6,%7}, {%8,%9}, {%0,%1,%2,%3};"
                 : "+f"(d[0]), "+f"(d[1]), "+f"(d[2]), "+f"(d[3])
                 : "r"(a[0]), "r"(a[1]), "r"(a[2]), "r"(a[3]), "r"(b0), "r"(b1));
}

// ---------------- kernel 2: persistent bf16 MMA GEMM + amortized epilogue ----
#define LDA 72                          // 64 + 8 pad (bf16 elems); row = 144 B
#define HALF_B  (128 * LDA * 2)         // 18432 B
#define STAGE_B (2 * HALF_B)            // 36864 B
// smem layout (from 1024-aligned base):
#define OFF_ST0  0                      // stage buffer 0 (A half + B half)
#define OFF_ST1  36864                  // stage buffer 1
#define OFF_RMP  73728                  // rm: [128][64] unsigned = 32768 B
#define OFF_CMP  106496                 // cm: [128][CSLOTS] unsigned = 4096 B
#define OFF_GNCP 110592                 // gnc: [128] int = 512 B
#define OFF_GLCP 111104                 // glc: [2][128] int = 1024 B
#define SMEM_GM  (112128 + 1024)

__global__ void __launch_bounds__(256, 2)
gemm_persist_kernel(const int* __restrict__ nbatch,
                    const int* __restrict__ lbatch) {
    extern __shared__ char dsm_raw[];
    const uint32_t sraw = (uint32_t)__cvta_generic_to_shared(dsm_raw);
    const uint32_t s0 = (sraw + 1023u) & ~1023u;
    char* p0 = dsm_raw + (s0 - sraw);

    unsigned* rm  = (unsigned*)(p0 + OFF_RMP);   // [128][64]
    unsigned* cm  = (unsigned*)(p0 + OFF_CMP);   // [128][CSLOTS]
    int*      gnc = (int*)     (p0 + OFF_GNCP);  // [128]
    int*      glc = (int*)     (p0 + OFF_GLCP);  // [2][128]

    const int tid  = threadIdx.x;
    const int wid  = tid >> 5;
    const int lane = tid & 31;
    const int wr = wid & 1;
    const int wc = wid >> 1;
    const int wrBase = wr * 64;
    const int wcBase = wc * 32;

    const int aRow = (lane & 7) + ((lane >> 3) & 1) * 8;
    const int aK   = (lane >> 4) * 8;
    const int bRow = (lane & 7) + (lane >> 4) * 8;
    const int bK   = ((lane >> 3) & 1) * 8;
    const int g  = lane >> 2;
    const int t2 = (lane & 3) * 2;

    const int cta = blockIdx.x;
    const int t0 = (int)(((long long)cta * NTILES) / GRID_P);
    const int t1 = (int)(((long long)(cta + 1) * NTILES) / GRID_P);

    int curI = -1;
    int lrows[8], grows[8];
    float nav[8];
    int gn_lo = 0;
    bool fastN = true;

    for (int t = t0; t < t1; ++t) {
        const int tp = t & 1;
        const int tileI = (t >> 6) * 128;
        const int tileJ = (t & 63) * 128;

        // first tile: issue stage0 + glc (later tiles have it prefetched)
        if (t == t0) {
            uint32_t st = s0 + OFF_ST0;
            #pragma unroll
            for (int it = 0; it < 4; ++it) {
                int id = it * 256 + tid;
                int r = id >> 3, kq = (id & 7) * 8;
                uint32_t d = (uint32_t)(r * LDA + kq) * 2;
                cp16(st + d,          g_efn_bf + (size_t)(tileI + r) * DD + kq);
                cp16(st + HALF_B + d, g_efl_bf + (size_t)(tileJ + r) * DD + kq);
            }
            if (tid < 128) glc[tp * 128 + tid] = lbatch[tileJ + tid];
            cp_commit();
        }

        // I-stripe change: flush + reinit persistent row staging, reload row meta
        if (tileI != curI) {
            if (curI >= 0) {
                // previous tile ended with __syncthreads(); rm is stable
                for (int x = tid; x < 128 * NG; x += 256) {
                    unsigned k = rm[x];
                    if (k != SENTINEL)
                        atomicMin(&g_rowmin[(size_t)(curI + (x >> 6)) * NG + (x & 63)], k);
                }
            }
            for (int x = tid; x < 128 * NG; x += 256) rm[x] = SENTINEL;
            if (tid < 128) gnc[tid] = nbatch[tileI + tid];
            __syncthreads();
            #pragma unroll
            for (int m = 0; m < 8; m++) {
                lrows[m] = wrBase + (m >> 1) * 16 + g + (m & 1) * 8;
                grows[m] = gnc[lrows[m]];
                nav[m]   = g_na[tileI + lrows[m]];
            }
            gn_lo = gnc[0];
            fastN = (gnc[127] - gn_lo) < CSLOTS;
            curI = tileI;
        }

        // clear col staging (visibility covered by first pipeline sync)
        #pragma unroll
        for (int x = tid; x < 128 * CSLOTS; x += 256) cm[x] = SENTINEL;

        float c[4][4][4];
        #pragma unroll
        for (int mi = 0; mi < 4; mi++)
            #pragma unroll
            for (int ni = 0; ni < 4; ni++)
                #pragma unroll
                for (int q = 0; q < 4; q++) c[mi][ni][q] = 0.f;

        // ---- 4-stage BK=64 pipeline, 2 buffers; cross-tile prefetch at s=3 ----
        const int NS = DD / 64;  // 4
        for (int s = 0; s < NS; ++s) {
            cp_wait0();
            __syncthreads();
            if (s + 1 < NS) {
                uint32_t st = s0 + ((s + 1) & 1 ? OFF_ST1 : OFF_ST0);
                int ko = (s + 1) * 64;
                #pragma unroll
                for (int it = 0; it < 4; ++it) {
                    int id = it * 256 + tid;
                    int r = id >> 3, kq = (id & 7) * 8;
                    uint32_t d = (uint32_t)(r * LDA + kq) * 2;
                    cp16(st + d,          g_efn_bf + (size_t)(tileI + r) * DD + ko + kq);
                    cp16(st + HALF_B + d, g_efl_bf + (size_t)(tileJ + r) * DD + ko + kq);
                }
                cp_commit();
            } else if (t + 1 < t1) {
                // prefetch next tile's stage 0 into buffer 0 (free after s=2)
                int ntI = ((t + 1) >> 6) * 128;
                int ntJ = ((t + 1) & 63) * 128;
                uint32_t st = s0 + OFF_ST0;
                #pragma unroll
                for (int it = 0; it < 4; ++it) {
                    int id = it * 256 + tid;
                    int r = id >> 3, kq = (id & 7) * 8;
                    uint32_t d = (uint32_t)(r * LDA + kq) * 2;
                    cp16(st + d,          g_efn_bf + (size_t)(ntI + r) * DD + kq);
                    cp16(st + HALF_B + d, g_efl_bf + (size_t)(ntJ + r) * DD + kq);
                }
                if (tid < 128) glc[(tp ^ 1) * 128 + tid] = lbatch[ntJ + tid];
                cp_commit();
            }
            uint32_t sA = s0 + ((s & 1) ? OFF_ST1 : OFF_ST0);
            uint32_t sB = sA + HALF_B;
            #pragma unroll
            for (int kb = 0; kb < 64; kb += 16) {
                uint32_t a[4][4];
                #pragma unroll
                for (int mi = 0; mi < 4; mi++)
                    ldmx4(a[mi], sA + (uint32_t)((wrBase + mi * 16 + aRow) * LDA + kb + aK) * 2);
                uint32_t b[2][4];
                #pragma unroll
                for (int nq = 0; nq < 2; nq++)
                    ldmx4(b[nq], sB + (uint32_t)((wcBase + nq * 16 + bRow) * LDA + kb + bK) * 2);
                #pragma unroll
                for (int mi = 0; mi < 4; mi++) {
                    #pragma unroll
                    for (int nq = 0; nq < 2; nq++) {
                        mma16816(c[mi][nq * 2 + 0], a[mi], b[nq][0], b[nq][1]);
                        mma16816(c[mi][nq * 2 + 1], a[mi], b[nq][2], b[nq][3]);
                    }
                }
            }
        }

        // ---- epilogue ----
        const int* glcc = glc + tp * 128;
        const int gl_loT = glcc[0];  (void)gl_loT;

        int   lcols[8], gcols[8];
        float nbv[8];
        #pragma unroll
        for (int n = 0; n < 8; n++) {
            lcols[n] = wcBase + (n >> 1) * 8 + t2 + (n & 1);
            gcols[n] = glcc[lcols[n]];
            nbv[n]   = g_nb[tileJ + lcols[n]];
        }

        // row-side: direct into persistent rm[row][gl]
        #pragma unroll
        for (int m = 0; m < 8; m++) {
            const int mi = m >> 1, hh = m & 1;
            float rbest = INF_F;
            int curgl = -1;
            #pragma unroll
            for (int n = 0; n < 8; n++) {
                const int ni = n >> 1, u = n & 1;
                float rv = fmaf(-2.f, c[mi][ni][hh * 2 + u], nbv[n]);
                int gg = gcols[n];
                if (gg != curgl) {
                    if (curgl >= 0)
                        atomicMin(&rm[lrows[m] * NG + curgl], encf(rbest));
                    curgl = gg; rbest = rv;
                } else {
                    rbest = fminf(rbest, rv);
                }
            }
            atomicMin(&rm[lrows[m] * NG + curgl], encf(rbest));
        }

        // col-side: cm staging (CSLOTS) with direct-global fallback
        {
            float cb[8];
            #pragma unroll
            for (int n = 0; n < 8; n++) cb[n] = INF_F;
            int curgn = -1;
            #pragma unroll
            for (int m = 0; m < 8; m++) {
                const int mi = m >> 1, hh = m & 1;
                int gi = grows[m];
                if (gi != curgn) {
                    if (curgn >= 0) {
                        #pragma unroll
                        for (int n = 0; n < 8; n++) {
                            unsigned k = encf(cb[n]);
                            if (fastN) atomicMin(&cm[lcols[n] * CSLOTS + (curgn - gn_lo)], k);
                            else       atomicMin(&g_colmin[(size_t)curgn * EL + tileJ + lcols[n]], k);
                            cb[n] = INF_F;
                        }
                    }
                    curgn = gi;
                }
                #pragma unroll
                for (int n = 0; n < 8; n++) {
                    const int ni = n >> 1, u = n & 1;
                    cb[n] = fminf(cb[n], fmaf(-2.f, c[mi][ni][hh * 2 + u], nav[m]));
                }
            }
            #pragma unroll
            for (int n = 0; n < 8; n++) {
                unsigned k = encf(cb[n]);
                if (fastN) atomicMin(&cm[lcols[n] * CSLOTS + (curgn - gn_lo)], k);
                else       atomicMin(&g_colmin[(size_t)curgn * EL + tileJ + lcols[n]], k);
            }
        }
        __syncthreads();

        // flush col staging (per tile)
        if (fastN) {
            #pragma unroll
            for (int x = tid; x < 128 * CSLOTS; x += 256) {
                int cc = x >> 3, sl = x & (CSLOTS - 1);
                unsigned k = cm[x];
                if (k != SENTINEL)
                    atomicMin(&g_colmin[(size_t)(gn_lo + sl) * EL + tileJ + cc], k);
            }
        }
        __syncthreads();
    }

    // final flush of persistent row staging
    if (curI >= 0) {
        for (int x = tid; x < 128 * NG; x += 256) {
            unsigned k = rm[x];
            if (k != SENTINEL)
                atomicMin(&g_rowmin[(size_t)(curI + (x >> 6)) * NG + (x & 63)], k);
        }
    }
}

// ---------------- small kernels (R10, frozen) --------------------------------
__global__ void hist_kernel(const int* __restrict__ nbatch,
                            const int* __restrict__ lbatch) {
    int idx = blockIdx.x * blockDim.x + threadIdx.x;
    if (idx < EN) atomicAdd(&g_cntn[nbatch[idx]], 1);
    else if (idx < EN + EL) atomicAdd(&g_cntl[lbatch[idx - EN]], 1);
}

__global__ void row_sum_kernel(const int* __restrict__ nbatch) {
    int gl = blockIdx.x;
    int base = blockIdx.y * 512;
    int t = threadIdx.x;
    #pragma unroll
    for (int it = 0; it < 2; ++it) {
        int i = base + it * 256 + t;
        unsigned k = g_rowmin[(size_t)i * NG + gl];
        float val = 0.f;
        if (k != SENTINEL) val = -sqrtf(fmaxf(g_na[i] + decf(k), 0.f));
        int gn = nbatch[i];
        int gn0 = __shfl_sync(0xffffffffu, gn, 0);
        if (__all_sync(0xffffffffu, gn == gn0)) {
            #pragma unroll
            for (int o = 16; o > 0; o >>= 1) val += __shfl_down_sync(0xffffffffu, val, o);
            if ((t & 31) == 0) atomicAdd(&g_sumn[gn0 * NG + gl], val);
        } else {
            atomicAdd(&g_sumn[gn * NG + gl], val);
        }
    }
}

__global__ void col_sum_kernel(const int* __restrict__ lbatch) {
    int gn = blockIdx.x;
    int base = blockIdx.y * 512;
    int t = threadIdx.x;
    #pragma unroll
    for (int it = 0; it < 2; ++it) {
        int j = base + it * 256 + t;
        unsigned k = g_colmin[(size_t)gn * EL + j];
        float val = 0.f;
        if (k != SENTINEL) val = -sqrtf(fmaxf(g_nb[j] + decf(k), 0.f));
        int gl = lbatch[j];
        int gl0 = __shfl_sync(0xffffffffu, gl, 0);
        if (__all_sync(0xffffffffu, gl == gl0)) {
            #pragma unroll
            for (int o = 16; o > 0; o >>= 1) val += __shfl_down_sync(0xffffffffu, val, o);
            if ((t & 31) == 0) atomicAdd(&g_suml[gn * NG + gl0], val);
        } else {
            atomicAdd(&g_suml[gn * NG + gl], val);
        }
    }
}

__global__ void combine_kernel(float* __restrict__ out) {
    int idx = blockIdx.x * blockDim.x + threadIdx.x;
    if (idx < NG * NG) {
        int gn = idx >> 6, gl = idx & (NG - 1);
        float on = g_sumn[idx] / (float)max(g_cntn[gn], 1);
        float ol = g_suml[idx] / (float)max(g_cntl[gl], 1);
        out[idx] = 0.5f * (on + ol);
    }
}

// ---------------- launch -------------------------------------------------------
extern "C" void kernel_launch(void* const* d_in, const int* in_sizes, int n_in,
                              void* d_out, int out_size) {
    const float* h           = (const float*)d_in[0];
    const int*   node_edge   = (const int*)d_in[1];
    const int*   node_batch  = (const int*)d_in[2];
    const int*   label_edge  = (const int*)d_in[3];
    const int*   label_batch = (const int*)d_in[4];
    float* out = (float*)d_out;

    cudaFuncSetAttribute(gemm_persist_kernel,
                         cudaFuncAttributeMaxDynamicSharedMemorySize, SMEM_GM);

    init_mins_kernel<<<(EN * NG + 255) / 256, 256>>>();
    build_ef_kernel<<<EN, 256>>>(h, node_edge, 0);
    build_ef_kernel<<<EL, 256>>>(h, label_edge, 1);
    gemm_persist_kernel<<<GRID_P, 256, SMEM_GM>>>(node_batch, label_batch);
    hist_kernel<<<(EN + EL + 255) / 256, 256>>>(node_batch, label_batch);
    row_sum_kernel<<<dim3(NG, 16), 256>>>(node_batch);
    col_sum_kernel<<<dim3(NG, 16), 256>>>(label_batch);
    combine_kernel<<<(NG * NG + 255) / 256, 256>>>(out);
}

// round 16
// speedup vs baseline: 2.5760x; 1.1846x over previous
#include <cuda_runtime.h>
#include <cuda_bf16.h>
#include <cstdint>

#define EN 8192
#define EL 8192
#define DD 256
#define NG 64
#define RSLOT 8
#define CSLOT 4
#define GRID_P 296
#define NTILES 4096

// ---------------- scratch (device globals) ----------------------------------
__device__ __align__(128) __nv_bfloat16 g_efn_bf[EN * DD];
__device__ __align__(128) __nv_bfloat16 g_efl_bf[EL * DD];
__device__ __align__(128) float    g_na[EN];
__device__ __align__(128) float    g_nb[EL];
__device__ __align__(128) unsigned g_rowmin[EN * NG];   // [i][gl]
__device__ __align__(128) unsigned g_colmin[NG * EL];   // [gn][j]
__device__ __align__(128) float    g_sumn[NG * NG];
__device__ __align__(128) float    g_suml[NG * NG];
__device__ __align__(128) int      g_cntn[NG];
__device__ __align__(128) int      g_cntl[NG];

__device__ __forceinline__ unsigned encf(float f) {
    unsigned u = __float_as_uint(f);
    return (u & 0x80000000u) ? ~u : (u | 0x80000000u);
}
__device__ __forceinline__ float decf(unsigned k) {
    unsigned u = (k & 0x80000000u) ? (k & 0x7FFFFFFFu) : ~k;
    return __uint_as_float(u);
}

#define SENTINEL 0xFFFFFFFFu
#define INF_F __int_as_float(0x7f800000)

// ---------------- kernel 0 ---------------------------------------------------
__global__ void init_mins_kernel() {
    int i = blockIdx.x * blockDim.x + threadIdx.x;
    if (i < EN * NG) {
        g_rowmin[i] = SENTINEL;
        g_colmin[i] = SENTINEL;
    }
    if (i < NG * NG) { g_sumn[i] = 0.f; g_suml[i] = 0.f; }
    if (i < NG)      { g_cntn[i] = 0;   g_cntl[i] = 0; }
}

// ---------------- kernel 1 ---------------------------------------------------
__global__ void build_ef_kernel(const float* __restrict__ h,
                                const int* __restrict__ edge,
                                int which) {
    __nv_bfloat16* ef = which ? g_efl_bf : g_efn_bf;
    float* nrm        = which ? g_nb     : g_na;
    int e = blockIdx.x;
    int t = threadIdx.x;
    int i0 = edge[e];
    int i1 = edge[EN + e];
    float v = 0.5f * (h[(size_t)i0 * DD + t] + h[(size_t)i1 * DD + t]);
    ef[(size_t)e * DD + t] = __float2bfloat16_rn(v);
    float s = v * v;
    #pragma unroll
    for (int o = 16; o > 0; o >>= 1) s += __shfl_down_sync(0xffffffffu, s, o);
    __shared__ float ws[8];
    if ((t & 31) == 0) ws[t >> 5] = s;
    __syncthreads();
    if (t < 8) {
        float x = ws[t];
        #pragma unroll
        for (int o = 4; o > 0; o >>= 1) x += __shfl_down_sync(0xffu, x, o);
        if (t == 0) nrm[e] = x;
    }
}

// ---------------- PTX helpers -------------------------------------------------
__device__ __forceinline__ void cp16(uint32_t dst, const void* src) {
    asm volatile("cp.async.cg.shared.global [%0], [%1], 16;" :: "r"(dst), "l"(src));
}
__device__ __forceinline__ void cp_commit() { asm volatile("cp.async.commit_group;"); }
__device__ __forceinline__ void cp_wait0()  { asm volatile("cp.async.wait_group 0;"); }
__device__ __forceinline__ void ldmx4(uint32_t* r, uint32_t addr) {
    asm volatile("ldmatrix.sync.aligned.m8n8.x4.shared.b16 {%0,%1,%2,%3}, [%4];"
                 : "=r"(r[0]), "=r"(r[1]), "=r"(r[2]), "=r"(r[3]) : "r"(addr));
}
__device__ __forceinline__ void mma16816(float* d, const uint32_t* a,
                                         uint32_t b0, uint32_t b1) {
    asm volatile("mma.sync.aligned.m16n8k16.row.col.f32.bf16.bf16.f32 "
                 "{%0,%1,%2,%3}, {%4,%5,%6,%7}, {%8,%9}, {%0,%1,%2,%3};"
                 : "+f"(d[0]), "+f"(d[1]), "+f"(d[2]), "+f"(d[3])
                 : "r"(a[0]), "r"(a[1]), "r"(a[2]), "r"(a[3]), "r"(b0), "r"(b1));
}

// ---------------- kernel 2: persistent GEMM, A-resident stripe ---------------
#define LDAR 264                        // A resident row: 256 + 8 pad
#define LDA  72                         // B stage row: 64 + 8 pad
#define BHALF (128 * LDA * 2)           // 18432 B per B stage
// smem layout from 1024-aligned base:
#define OFF_AR  0                       // 128*264*2 = 67584
#define OFF_B0  67584
#define OFF_B1  86016
#define OFF_RM  104448                  // [128][RSLOT] u32 = 4096
#define OFF_CM  108544                  // [128][CSLOT] u32 = 2048
#define OFF_GNC 110592                  // [128] int
#define OFF_GLC 111104                  // [2][128] int
#define SMEM_GM (112128 + 1024)         // 113152 <= 114688 (14 x 8KB units)

__global__ void __launch_bounds__(256, 2)
gemm_persist_kernel(const int* __restrict__ nbatch,
                    const int* __restrict__ lbatch) {
    extern __shared__ char dsm_raw[];
    const uint32_t sraw = (uint32_t)__cvta_generic_to_shared(dsm_raw);
    const uint32_t s0 = (sraw + 1023u) & ~1023u;
    char* p0 = dsm_raw + (s0 - sraw);

    unsigned* rm  = (unsigned*)(p0 + OFF_RM);
    unsigned* cm  = (unsigned*)(p0 + OFF_CM);
    int*      gnc = (int*)     (p0 + OFF_GNC);
    int*      glc = (int*)     (p0 + OFF_GLC);

    const int tid  = threadIdx.x;
    const int wid  = tid >> 5;
    const int lane = tid & 31;
    const int wr = wid & 1;
    const int wc = wid >> 1;
    const int wrBase = wr * 64;
    const int wcBase = wc * 32;

    const int aRow = (lane & 7) + ((lane >> 3) & 1) * 8;
    const int aK   = (lane >> 4) * 8;
    const int bRow = (lane & 7) + (lane >> 4) * 8;
    const int bK   = ((lane >> 3) & 1) * 8;
    const int g  = lane >> 2;
    const int t2 = (lane & 3) * 2;

    const int cta = blockIdx.x;
    const int t0 = (int)(((long long)cta * NTILES) / GRID_P);
    const int t1 = (int)(((long long)(cta + 1) * NTILES) / GRID_P);

    int curI = -1;
    int lrows[8], grows[8];
    float nav[8];
    int gn_lo = 0;
    bool fastN = true;

    for (int t = t0; t < t1; ++t) {
        const int tp = t & 1;
        const int tileI = (t >> 6) * 128;
        const int tileJ = (t & 63) * 128;

        // first tile of this CTA: B stage0 + glc not yet prefetched
        if (t == t0) {
            uint32_t st = s0 + OFF_B0;
            #pragma unroll
            for (int it = 0; it < 4; ++it) {
                int id = it * 256 + tid;
                int r = id >> 3, kq = (id & 7) * 8;
                cp16(st + (uint32_t)(r * LDA + kq) * 2,
                     g_efl_bf + (size_t)(tileJ + r) * DD + kq);
            }
            if (tid < 128) glc[tp * 128 + tid] = lbatch[tileJ + tid];
            cp_commit();
        }

        // I-stripe change: load resident A stripe + row metadata
        if (tileI != curI) {
            #pragma unroll
            for (int it = 0; it < 16; ++it) {
                int id = it * 256 + tid;
                int r = id >> 5, kk = id & 31;
                cp16(s0 + OFF_AR + (uint32_t)(r * LDAR + kk * 8) * 2,
                     g_efn_bf + (size_t)(tileI + r) * DD + kk * 8);
            }
            cp_commit();
            if (tid < 128) gnc[tid] = nbatch[tileI + tid];
            __syncthreads();
            #pragma unroll
            for (int m = 0; m < 8; m++) {
                lrows[m] = wrBase + (m >> 1) * 16 + g + (m & 1) * 8;
                grows[m] = gnc[lrows[m]];
                nav[m]   = g_na[tileI + lrows[m]];
            }
            gn_lo = gnc[0];
            fastN = (gnc[127] - gn_lo) < CSLOT;
            curI = tileI;
        }

        // init per-tile staging (visibility covered by first pipeline sync)
        #pragma unroll
        for (int x = tid; x < 128 * RSLOT; x += 256) rm[x] = SENTINEL;
        #pragma unroll
        for (int x = tid; x < 128 * CSLOT; x += 256) cm[x] = SENTINEL;

        float c[4][4][4];
        #pragma unroll
        for (int mi = 0; mi < 4; mi++)
            #pragma unroll
            for (int ni = 0; ni < 4; ni++)
                #pragma unroll
                for (int q = 0; q < 4; q++) c[mi][ni][q] = 0.f;

        // ---- 4 stages of BK=64; B double-buffered; A read from resident ----
        const int NS = DD / 64;
        for (int s = 0; s < NS; ++s) {
            cp_wait0();
            __syncthreads();
            if (s + 1 < NS) {
                uint32_t st = s0 + ((s + 1) & 1 ? OFF_B1 : OFF_B0);
                int ko = (s + 1) * 64;
                #pragma unroll
                for (int it = 0; it < 4; ++it) {
                    int id = it * 256 + tid;
                    int r = id >> 3, kq = (id & 7) * 8;
                    cp16(st + (uint32_t)(r * LDA + kq) * 2,
                         g_efl_bf + (size_t)(tileJ + r) * DD + ko + kq);
                }
                cp_commit();
            } else if (t + 1 < t1) {
                int ntJ = ((t + 1) & 63) * 128;
                uint32_t st = s0 + OFF_B0;
                #pragma unroll
                for (int it = 0; it < 4; ++it) {
                    int id = it * 256 + tid;
                    int r = id >> 3, kq = (id & 7) * 8;
                    cp16(st + (uint32_t)(r * LDA + kq) * 2,
                         g_efl_bf + (size_t)(ntJ + r) * DD + kq);
                }
                if (tid < 128) glc[(tp ^ 1) * 128 + tid] = lbatch[ntJ + tid];
                cp_commit();
            }
            uint32_t sAr = s0 + OFF_AR;
            uint32_t sB  = s0 + ((s & 1) ? OFF_B1 : OFF_B0);
            const int koff = s * 64;
            #pragma unroll
            for (int kb = 0; kb < 64; kb += 16) {
                uint32_t a[4][4];
                #pragma unroll
                for (int mi = 0; mi < 4; mi++)
                    ldmx4(a[mi], sAr + (uint32_t)((wrBase + mi * 16 + aRow) * LDAR + koff + kb + aK) * 2);
                uint32_t b[2][4];
                #pragma unroll
                for (int nq = 0; nq < 2; nq++)
                    ldmx4(b[nq], sB + (uint32_t)((wcBase + nq * 16 + bRow) * LDA + kb + bK) * 2);
                #pragma unroll
                for (int mi = 0; mi < 4; mi++) {
                    #pragma unroll
                    for (int nq = 0; nq < 2; nq++) {
                        mma16816(c[mi][nq * 2 + 0], a[mi], b[nq][0], b[nq][1]);
                        mma16816(c[mi][nq * 2 + 1], a[mi], b[nq][2], b[nq][3]);
                    }
                }
            }
        }

        // ---- epilogue ----
        const int* glcc = glc + tp * 128;
        const int gl_lo = glcc[0];
        const bool fastL = (glcc[127] - gl_lo) < RSLOT;

        int   lcols[8], gcols[8];
        float nbv[8];
        #pragma unroll
        for (int n = 0; n < 8; n++) {
            lcols[n] = wcBase + (n >> 1) * 8 + t2 + (n & 1);
            gcols[n] = glcc[lcols[n]];
            nbv[n]   = g_nb[tileJ + lcols[n]];
        }

        // row-side
        #pragma unroll
        for (int m = 0; m < 8; m++) {
            const int mi = m >> 1, hh = m & 1;
            float rbest = INF_F;
            int curgl = -1;
            #pragma unroll
            for (int n = 0; n < 8; n++) {
                const int ni = n >> 1, u = n & 1;
                float rv = fmaf(-2.f, c[mi][ni][hh * 2 + u], nbv[n]);
                int gg = gcols[n];
                if (gg != curgl) {
                    if (curgl >= 0) {
                        unsigned k = encf(rbest);
                        if (fastL) atomicMin(&rm[lrows[m] * RSLOT + (curgl - gl_lo)], k);
                        else       atomicMin(&g_rowmin[(size_t)(tileI + lrows[m]) * NG + curgl], k);
                    }
                    curgl = gg; rbest = rv;
                } else {
                    rbest = fminf(rbest, rv);
                }
            }
            unsigned k = encf(rbest);
            if (fastL) atomicMin(&rm[lrows[m] * RSLOT + (curgl - gl_lo)], k);
            else       atomicMin(&g_rowmin[(size_t)(tileI + lrows[m]) * NG + curgl], k);
        }

        // col-side
        {
            float cb[8];
            #pragma unroll
            for (int n = 0; n < 8; n++) cb[n] = INF_F;
            int curgn = -1;
            #pragma unroll
            for (int m = 0; m < 8; m++) {
                const int mi = m >> 1, hh = m & 1;
                int gi = grows[m];
                if (gi != curgn) {
                    if (curgn >= 0) {
                        #pragma unroll
                        for (int n = 0; n < 8; n++) {
                            unsigned k = encf(cb[n]);
                            if (fastN) atomicMin(&cm[lcols[n] * CSLOT + (curgn - gn_lo)], k);
                            else       atomicMin(&g_colmin[(size_t)curgn * EL + tileJ + lcols[n]], k);
                            cb[n] = INF_F;
                        }
                    }
                    curgn = gi;
                }
                #pragma unroll
                for (int n = 0; n < 8; n++) {
                    const int ni = n >> 1, u = n & 1;
                    cb[n] = fminf(cb[n], fmaf(-2.f, c[mi][ni][hh * 2 + u], nav[m]));
                }
            }
            #pragma unroll
            for (int n = 0; n < 8; n++) {
                unsigned k = encf(cb[n]);
                if (fastN) atomicMin(&cm[lcols[n] * CSLOT + (curgn - gn_lo)], k);
                else       atomicMin(&g_colmin[(size_t)curgn * EL + tileJ + lcols[n]], k);
            }
        }
        __syncthreads();

        // flush per-tile staging
        if (fastL) {
            #pragma unroll
            for (int x = tid; x < 128 * RSLOT; x += 256) {
                int r = x >> 3, sl = x & (RSLOT - 1);
                unsigned k = rm[x];
                if (k != SENTINEL)
                    atomicMin(&g_rowmin[(size_t)(tileI + r) * NG + gl_lo + sl], k);
            }
        }
        if (fastN) {
            #pragma unroll
            for (int x = tid; x < 128 * CSLOT; x += 256) {
                int cc = x >> 2, sl = x & (CSLOT - 1);
                unsigned k = cm[x];
                if (k != SENTINEL)
                    atomicMin(&g_colmin[(size_t)(gn_lo + sl) * EL + tileJ + cc], k);
            }
        }
        __syncthreads();
    }
}

// ---------------- small kernels (R10, frozen) --------------------------------
__global__ void hist_kernel(const int* __restrict__ nbatch,
                            const int* __restrict__ lbatch) {
    int idx = blockIdx.x * blockDim.x + threadIdx.x;
    if (idx < EN) atomicAdd(&g_cntn[nbatch[idx]], 1);
    else if (idx < EN + EL) atomicAdd(&g_cntl[lbatch[idx - EN]], 1);
}

__global__ void row_sum_kernel(const int* __restrict__ nbatch) {
    int gl = blockIdx.x;
    int base = blockIdx.y * 512;
    int t = threadIdx.x;
    #pragma unroll
    for (int it = 0; it < 2; ++it) {
        int i = base + it * 256 + t;
        unsigned k = g_rowmin[(size_t)i * NG + gl];
        float val = 0.f;
        if (k != SENTINEL) val = -sqrtf(fmaxf(g_na[i] + decf(k), 0.f));
        int gn = nbatch[i];
        int gn0 = __shfl_sync(0xffffffffu, gn, 0);
        if (__all_sync(0xffffffffu, gn == gn0)) {
            #pragma unroll
            for (int o = 16; o > 0; o >>= 1) val += __shfl_down_sync(0xffffffffu, val, o);
            if ((t & 31) == 0) atomicAdd(&g_sumn[gn0 * NG + gl], val);
        } else {
            atomicAdd(&g_sumn[gn * NG + gl], val);
        }
    }
}

__global__ void col_sum_kernel(const int* __restrict__ lbatch) {
    int gn = blockIdx.x;
    int base = blockIdx.y * 512;
    int t = threadIdx.x;
    #pragma unroll
    for (int it = 0; it < 2; ++it) {
        int j = base + it * 256 + t;
        unsigned k = g_colmin[(size_t)gn * EL + j];
        float val = 0.f;
        if (k != SENTINEL) val = -sqrtf(fmaxf(g_nb[j] + decf(k), 0.f));
        int gl = lbatch[j];
        int gl0 = __shfl_sync(0xffffffffu, gl, 0);
        if (__all_sync(0xffffffffu, gl == gl0)) {
            #pragma unroll
            for (int o = 16; o > 0; o >>= 1) val += __shfl_down_sync(0xffffffffu, val, o);
            if ((t & 31) == 0) atomicAdd(&g_suml[gn * NG + gl0], val);
        } else {
            atomicAdd(&g_suml[gn * NG + gl], val);
        }
    }
}

__global__ void combine_kernel(float* __restrict__ out) {
    int idx = blockIdx.x * blockDim.x + threadIdx.x;
    if (idx < NG * NG) {
        int gn = idx >> 6, gl = idx & (NG - 1);
        float on = g_sumn[idx] / (float)max(g_cntn[gn], 1);
        float ol = g_suml[idx] / (float)max(g_cntl[gl], 1);
        out[idx] = 0.5f * (on + ol);
    }
}

// ---------------- launch -------------------------------------------------------
extern "C" void kernel_launch(void* const* d_in, const int* in_sizes, int n_in,
                              void* d_out, int out_size) {
    const float* h           = (const float*)d_in[0];
    const int*   node_edge   = (const int*)d_in[1];
    const int*   node_batch  = (const int*)d_in[2];
    const int*   label_edge  = (const int*)d_in[3];
    const int*   label_batch = (const int*)d_in[4];
    float* out = (float*)d_out;

    cudaFuncSetAttribute(gemm_persist_kernel,
                         cudaFuncAttributeMaxDynamicSharedMemorySize, SMEM_GM);

    init_mins_kernel<<<(EN * NG + 255) / 256, 256>>>();
    build_ef_kernel<<<EN, 256>>>(h, node_edge, 0);
    build_ef_kernel<<<EL, 256>>>(h, label_edge, 1);
    gemm_persist_kernel<<<GRID_P, 256, SMEM_GM>>>(node_batch, label_batch);
    hist_kernel<<<(EN + EL + 255) / 256, 256>>>(node_batch, label_batch);
    row_sum_kernel<<<dim3(NG, 16), 256>>>(node_batch);
    col_sum_kernel<<<dim3(NG, 16), 256>>>(label_batch);
    combine_kernel<<<(NG * NG + 255) / 256, 256>>>(out);
}

// round 17
// speedup vs baseline: 2.7340x; 1.0613x over previous
#include <cuda_runtime.h>
#include <cuda_bf16.h>
#include <cstdint>

#define EN 8192
#define EL 8192
#define DD 256
#define NG 64
#define RSLOT 8
#define CSLOT 4
#define GRID_P 296
#define NTILES 4096

// ---------------- scratch (device globals) ----------------------------------
__device__ __align__(128) __nv_bfloat16 g_efn_bf[EN * DD];
__device__ __align__(128) __nv_bfloat16 g_efl_bf[EL * DD];
__device__ __align__(128) float    g_na[EN];
__device__ __align__(128) float    g_nb[EL];
__device__ __align__(128) unsigned g_rowmin[EN * NG];   // [i][gl]
__device__ __align__(128) unsigned g_colmin[NG * EL];   // [gn][j]
__device__ __align__(128) float    g_sumn[NG * NG];
__device__ __align__(128) float    g_suml[NG * NG];
__device__ __align__(128) int      g_cntn[NG];
__device__ __align__(128) int      g_cntl[NG];

__device__ __forceinline__ unsigned encf(float f) {
    unsigned u = __float_as_uint(f);
    return (u & 0x80000000u) ? ~u : (u | 0x80000000u);
}
__device__ __forceinline__ float decf(unsigned k) {
    unsigned u = (k & 0x80000000u) ? (k & 0x7FFFFFFFu) : ~k;
    return __uint_as_float(u);
}

#define SENTINEL 0xFFFFFFFFu
#define INF_F __int_as_float(0x7f800000)

// ---------------- kernel 0: uint4 reset of min buffers ----------------------
__global__ void init_mins_kernel() {
    int i = blockIdx.x * blockDim.x + threadIdx.x;
    uint4 s = make_uint4(SENTINEL, SENTINEL, SENTINEL, SENTINEL);
    if (i < EN * NG / 4) {
        ((uint4*)g_rowmin)[i] = s;
        ((uint4*)g_colmin)[i] = s;
    }
    if (i < NG * NG) { g_sumn[i] = 0.f; g_suml[i] = 0.f; }
    if (i < NG)      { g_cntn[i] = 0;   g_cntl[i] = 0; }
}

// ---------------- kernel 1: fused + vectorized ef build ----------------------
// grid 4096: blocks [0,2048) node edges, [2048,4096) label edges.
// 4 edges per 256-thread block; 64 threads (float4 lanes) per edge.
__global__ void build_ef_kernel(const float* __restrict__ h,
                                const int* __restrict__ nedge,
                                const int* __restrict__ ledge) {
    const int half = blockIdx.x >> 11;
    const int* edge   = half ? ledge    : nedge;
    __nv_bfloat16* ef = half ? g_efl_bf : g_efn_bf;
    float* nrm        = half ? g_nb     : g_na;
    const int bb = blockIdx.x & 2047;
    const int t = threadIdx.x;
    const int e = bb * 4 + (t >> 6);
    const int q = t & 63;
    const float4* h4 = (const float4*)h;
    int i0 = edge[e];
    int i1 = edge[EN + e];
    float4 a = __ldg(&h4[(size_t)i0 * 64 + q]);
    float4 b = __ldg(&h4[(size_t)i1 * 64 + q]);
    float4 v;
    v.x = 0.5f * (a.x + b.x); v.y = 0.5f * (a.y + b.y);
    v.z = 0.5f * (a.z + b.z); v.w = 0.5f * (a.w + b.w);
    union { __nv_bfloat162 h2[2]; uint2 u; } pk;
    pk.h2[0] = __floats2bfloat162_rn(v.x, v.y);
    pk.h2[1] = __floats2bfloat162_rn(v.z, v.w);
    *(uint2*)(ef + (size_t)e * DD + q * 4) = pk.u;
    float s = v.x * v.x + v.y * v.y + v.z * v.z + v.w * v.w;
    #pragma unroll
    for (int o = 16; o > 0; o >>= 1) s += __shfl_down_sync(0xffffffffu, s, o);
    __shared__ float ws[8];
    if ((t & 31) == 0) ws[t >> 5] = s;
    __syncthreads();
    if (t < 4) nrm[bb * 4 + t] = ws[2 * t] + ws[2 * t + 1];
}

// ---------------- PTX helpers -------------------------------------------------
__device__ __forceinline__ void cp16(uint32_t dst, const void* src) {
    asm volatile("cp.async.cg.shared.global [%0], [%1], 16;" :: "r"(dst), "l"(src));
}
__device__ __forceinline__ void cp_commit() { asm volatile("cp.async.commit_group;"); }
__device__ __forceinline__ void cp_wait0()  { asm volatile("cp.async.wait_group 0;"); }
__device__ __forceinline__ void ldmx4(uint32_t* r, uint32_t addr) {
    asm volatile("ldmatrix.sync.aligned.m8n8.x4.shared.b16 {%0,%1,%2,%3}, [%4];"
                 : "=r"(r[0]), "=r"(r[1]), "=r"(r[2]), "=r"(r[3]) : "r"(addr));
}
__device__ __forceinline__ void mma16816(float* d, const uint32_t* a,
                                         uint32_t b0, uint32_t b1) {
    asm volatile("mma.sync.aligned.m16n8k16.row.col.f32.bf16.bf16.f32 "
                 "{%0,%1,%2,%3}, {%4,%5,%6,%7}, {%8,%9}, {%0,%1,%2,%3};"
                 : "+f"(d[0]), "+f"(d[1]), "+f"(d[2]), "+f"(d[3])
                 : "r"(a[0]), "r"(a[1]), "r"(a[2]), "r"(a[3]), "r"(b0), "r"(b1));
}

// ---------------- kernel 2: persistent GEMM, A-resident stripe (FROZEN R16) --
#define LDAR 264
#define LDA  72
#define BHALF (128 * LDA * 2)
#define OFF_AR  0
#define OFF_B0  67584
#define OFF_B1  86016
#define OFF_RM  104448
#define OFF_CM  108544
#define OFF_GNC 110592
#define OFF_GLC 111104
#define SMEM_GM (112128 + 1024)

__global__ void __launch_bounds__(256, 2)
gemm_persist_kernel(const int* __restrict__ nbatch,
                    const int* __restrict__ lbatch) {
    extern __shared__ char dsm_raw[];
    const uint32_t sraw = (uint32_t)__cvta_generic_to_shared(dsm_raw);
    const uint32_t s0 = (sraw + 1023u) & ~1023u;
    char* p0 = dsm_raw + (s0 - sraw);

    unsigned* rm  = (unsigned*)(p0 + OFF_RM);
    unsigned* cm  = (unsigned*)(p0 + OFF_CM);
    int*      gnc = (int*)     (p0 + OFF_GNC);
    int*      glc = (int*)     (p0 + OFF_GLC);

    const int tid  = threadIdx.x;
    const int wid  = tid >> 5;
    const int lane = tid & 31;
    const int wr = wid & 1;
    const int wc = wid >> 1;
    const int wrBase = wr * 64;
    const int wcBase = wc * 32;

    const int aRow = (lane & 7) + ((lane >> 3) & 1) * 8;
    const int aK   = (lane >> 4) * 8;
    const int bRow = (lane & 7) + (lane >> 4) * 8;
    const int bK   = ((lane >> 3) & 1) * 8;
    const int g  = lane >> 2;
    const int t2 = (lane & 3) * 2;

    const int cta = blockIdx.x;
    const int t0 = (int)(((long long)cta * NTILES) / GRID_P);
    const int t1 = (int)(((long long)(cta + 1) * NTILES) / GRID_P);

    int curI = -1;
    int lrows[8], grows[8];
    float nav[8];
    int gn_lo = 0;
    bool fastN = true;

    for (int t = t0; t < t1; ++t) {
        const int tp = t & 1;
        const int tileI = (t >> 6) * 128;
        const int tileJ = (t & 63) * 128;

        if (t == t0) {
            uint32_t st = s0 + OFF_B0;
            #pragma unroll
            for (int it = 0; it < 4; ++it) {
                int id = it * 256 + tid;
                int r = id >> 3, kq = (id & 7) * 8;
                cp16(st + (uint32_t)(r * LDA + kq) * 2,
                     g_efl_bf + (size_t)(tileJ + r) * DD + kq);
            }
            if (tid < 128) glc[tp * 128 + tid] = lbatch[tileJ + tid];
            cp_commit();
        }

        if (tileI != curI) {
            #pragma unroll
            for (int it = 0; it < 16; ++it) {
                int id = it * 256 + tid;
                int r = id >> 5, kk = id & 31;
                cp16(s0 + OFF_AR + (uint32_t)(r * LDAR + kk * 8) * 2,
                     g_efn_bf + (size_t)(tileI + r) * DD + kk * 8);
            }
            cp_commit();
            if (tid < 128) gnc[tid] = nbatch[tileI + tid];
            __syncthreads();
            #pragma unroll
            for (int m = 0; m < 8; m++) {
                lrows[m] = wrBase + (m >> 1) * 16 + g + (m & 1) * 8;
                grows[m] = gnc[lrows[m]];
                nav[m]   = g_na[tileI + lrows[m]];
            }
            gn_lo = gnc[0];
            fastN = (gnc[127] - gn_lo) < CSLOT;
            curI = tileI;
        }

        #pragma unroll
        for (int x = tid; x < 128 * RSLOT; x += 256) rm[x] = SENTINEL;
        #pragma unroll
        for (int x = tid; x < 128 * CSLOT; x += 256) cm[x] = SENTINEL;

        float c[4][4][4];
        #pragma unroll
        for (int mi = 0; mi < 4; mi++)
            #pragma unroll
            for (int ni = 0; ni < 4; ni++)
                #pragma unroll
                for (int q = 0; q < 4; q++) c[mi][ni][q] = 0.f;

        const int NS = DD / 64;
        for (int s = 0; s < NS; ++s) {
            cp_wait0();
            __syncthreads();
            if (s + 1 < NS) {
                uint32_t st = s0 + ((s + 1) & 1 ? OFF_B1 : OFF_B0);
                int ko = (s + 1) * 64;
                #pragma unroll
                for (int it = 0; it < 4; ++it) {
                    int id = it * 256 + tid;
                    int r = id >> 3, kq = (id & 7) * 8;
                    cp16(st + (uint32_t)(r * LDA + kq) * 2,
                         g_efl_bf + (size_t)(tileJ + r) * DD + ko + kq);
                }
                cp_commit();
            } else if (t + 1 < t1) {
                int ntJ = ((t + 1) & 63) * 128;
                uint32_t st = s0 + OFF_B0;
                #pragma unroll
                for (int it = 0; it < 4; ++it) {
                    int id = it * 256 + tid;
                    int r = id >> 3, kq = (id & 7) * 8;
                    cp16(st + (uint32_t)(r * LDA + kq) * 2,
                         g_efl_bf + (size_t)(ntJ + r) * DD + kq);
                }
                if (tid < 128) glc[(tp ^ 1) * 128 + tid] = lbatch[ntJ + tid];
                cp_commit();
            }
            uint32_t sAr = s0 + OFF_AR;
            uint32_t sB  = s0 + ((s & 1) ? OFF_B1 : OFF_B0);
            const int koff = s * 64;
            #pragma unroll
            for (int kb = 0; kb < 64; kb += 16) {
                uint32_t a[4][4];
                #pragma unroll
                for (int mi = 0; mi < 4; mi++)
                    ldmx4(a[mi], sAr + (uint32_t)((wrBase + mi * 16 + aRow) * LDAR + koff + kb + aK) * 2);
                uint32_t b[2][4];
                #pragma unroll
                for (int nq = 0; nq < 2; nq++)
                    ldmx4(b[nq], sB + (uint32_t)((wcBase + nq * 16 + bRow) * LDA + kb + bK) * 2);
                #pragma unroll
                for (int mi = 0; mi < 4; mi++) {
                    #pragma unroll
                    for (int nq = 0; nq < 2; nq++) {
                        mma16816(c[mi][nq * 2 + 0], a[mi], b[nq][0], b[nq][1]);
                        mma16816(c[mi][nq * 2 + 1], a[mi], b[nq][2], b[nq][3]);
                    }
                }
            }
        }

        const int* glcc = glc + tp * 128;
        const int gl_lo = glcc[0];
        const bool fastL = (glcc[127] - gl_lo) < RSLOT;

        int   lcols[8], gcols[8];
        float nbv[8];
        #pragma unroll
        for (int n = 0; n < 8; n++) {
            lcols[n] = wcBase + (n >> 1) * 8 + t2 + (n & 1);
            gcols[n] = glcc[lcols[n]];
            nbv[n]   = g_nb[tileJ + lcols[n]];
        }

        #pragma unroll
        for (int m = 0; m < 8; m++) {
            const int mi = m >> 1, hh = m & 1;
            float rbest = INF_F;
            int curgl = -1;
            #pragma unroll
            for (int n = 0; n < 8; n++) {
                const int ni = n >> 1, u = n & 1;
                float rv = fmaf(-2.f, c[mi][ni][hh * 2 + u], nbv[n]);
                int gg = gcols[n];
                if (gg != curgl) {
                    if (curgl >= 0) {
                        unsigned k = encf(rbest);
                        if (fastL) atomicMin(&rm[lrows[m] * RSLOT + (curgl - gl_lo)], k);
                        else       atomicMin(&g_rowmin[(size_t)(tileI + lrows[m]) * NG + curgl], k);
                    }
                    curgl = gg; rbest = rv;
                } else {
                    rbest = fminf(rbest, rv);
                }
            }
            unsigned k = encf(rbest);
            if (fastL) atomicMin(&rm[lrows[m] * RSLOT + (curgl - gl_lo)], k);
            else       atomicMin(&g_rowmin[(size_t)(tileI + lrows[m]) * NG + curgl], k);
        }

        {
            float cb[8];
            #pragma unroll
            for (int n = 0; n < 8; n++) cb[n] = INF_F;
            int curgn = -1;
            #pragma unroll
            for (int m = 0; m < 8; m++) {
                const int mi = m >> 1, hh = m & 1;
                int gi = grows[m];
                if (gi != curgn) {
                    if (curgn >= 0) {
                        #pragma unroll
                        for (int n = 0; n < 8; n++) {
                            unsigned k = encf(cb[n]);
                            if (fastN) atomicMin(&cm[lcols[n] * CSLOT + (curgn - gn_lo)], k);
                            else       atomicMin(&g_colmin[(size_t)curgn * EL + tileJ + lcols[n]], k);
                            cb[n] = INF_F;
                        }
                    }
                    curgn = gi;
                }
                #pragma unroll
                for (int n = 0; n < 8; n++) {
                    const int ni = n >> 1, u = n & 1;
                    cb[n] = fminf(cb[n], fmaf(-2.f, c[mi][ni][hh * 2 + u], nav[m]));
                }
            }
            #pragma unroll
            for (int n = 0; n < 8; n++) {
                unsigned k = encf(cb[n]);
                if (fastN) atomicMin(&cm[lcols[n] * CSLOT + (curgn - gn_lo)], k);
                else       atomicMin(&g_colmin[(size_t)curgn * EL + tileJ + lcols[n]], k);
            }
        }
        __syncthreads();

        if (fastL) {
            #pragma unroll
            for (int x = tid; x < 128 * RSLOT; x += 256) {
                int r = x >> 3, sl = x & (RSLOT - 1);
                unsigned k = rm[x];
                if (k != SENTINEL)
                    atomicMin(&g_rowmin[(size_t)(tileI + r) * NG + gl_lo + sl], k);
            }
        }
        if (fastN) {
            #pragma unroll
            for (int x = tid; x < 128 * CSLOT; x += 256) {
                int cc = x >> 2, sl = x & (CSLOT - 1);
                unsigned k = cm[x];
                if (k != SENTINEL)
                    atomicMin(&g_colmin[(size_t)(gn_lo + sl) * EL + tileJ + cc], k);
            }
        }
        __syncthreads();
    }
}

// ---------------- small kernels -----------------------------------------------
__global__ void hist_kernel(const int* __restrict__ nbatch,
                            const int* __restrict__ lbatch) {
    int idx = blockIdx.x * blockDim.x + threadIdx.x;
    if (idx < EN) atomicAdd(&g_cntn[nbatch[idx]], 1);
    else if (idx < EN + EL) atomicAdd(&g_cntl[lbatch[idx - EN]], 1);
}

__global__ void row_sum_kernel(const int* __restrict__ nbatch) {
    int gl = blockIdx.x;
    int base = blockIdx.y * 512;
    int t = threadIdx.x;
    #pragma unroll
    for (int it = 0; it < 2; ++it) {
        int i = base + it * 256 + t;
        unsigned k = g_rowmin[(size_t)i * NG + gl];
        float val = 0.f;
        if (k != SENTINEL) val = -sqrtf(fmaxf(g_na[i] + decf(k), 0.f));
        int gn = nbatch[i];
        int gn0 = __shfl_sync(0xffffffffu, gn, 0);
        if (__all_sync(0xffffffffu, gn == gn0)) {
            #pragma unroll
            for (int o = 16; o > 0; o >>= 1) val += __shfl_down_sync(0xffffffffu, val, o);
            if ((t & 31) == 0) atomicAdd(&g_sumn[gn0 * NG + gl], val);
        } else {
            atomicAdd(&g_sumn[gn * NG + gl], val);
        }
    }
}

__global__ void col_sum_kernel(const int* __restrict__ lbatch) {
    int gn = blockIdx.x;
    int base = blockIdx.y * 512;
    int t = threadIdx.x;
    #pragma unroll
    for (int it = 0; it < 2; ++it) {
        int j = base + it * 256 + t;
        unsigned k = g_colmin[(size_t)gn * EL + j];
        float val = 0.f;
        if (k != SENTINEL) val = -sqrtf(fmaxf(g_nb[j] + decf(k), 0.f));
        int gl = lbatch[j];
        int gl0 = __shfl_sync(0xffffffffu, gl, 0);
        if (__all_sync(0xffffffffu, gl == gl0)) {
            #pragma unroll
            for (int o = 16; o > 0; o >>= 1) val += __shfl_down_sync(0xffffffffu, val, o);
            if ((t & 31) == 0) atomicAdd(&g_suml[gn * NG + gl0], val);
        } else {
            atomicAdd(&g_suml[gn * NG + gl], val);
        }
    }
}

__global__ void combine_kernel(float* __restrict__ out) {
    int idx = blockIdx.x * blockDim.x + threadIdx.x;
    if (idx < NG * NG) {
        int gn = idx >> 6, gl = idx & (NG - 1);
        float on = g_sumn[idx] / (float)max(g_cntn[gn], 1);
        float ol = g_suml[idx] / (float)max(g_cntl[gl], 1);
        out[idx] = 0.5f * (on + ol);
    }
}

// ---------------- launch -------------------------------------------------------
extern "C" void kernel_launch(void* const* d_in, const int* in_sizes, int n_in,
                              void* d_out, int out_size) {
    const float* h           = (const float*)d_in[0];
    const int*   node_edge   = (const int*)d_in[1];
    const int*   node_batch  = (const int*)d_in[2];
    const int*   label_edge  = (const int*)d_in[3];
    const int*   label_batch = (const int*)d_in[4];
    float* out = (float*)d_out;

    cudaFuncSetAttribute(gemm_persist_kernel,
                         cudaFuncAttributeMaxDynamicSharedMemorySize, SMEM_GM);

    init_mins_kernel<<<(EN * NG / 4 + 255) / 256, 256>>>();
    build_ef_kernel<<<4096, 256>>>(h, node_edge, label_edge);
    gemm_persist_kernel<<<GRID_P, 256, SMEM_GM>>>(node_batch, label_batch);
    hist_kernel<<<(EN + EL + 255) / 256, 256>>>(node_batch, label_batch);
    row_sum_kernel<<<dim3(NG, 16), 256>>>(node_batch);
    col_sum_kernel<<<dim3(NG, 16), 256>>>(label_batch);
    combine_kernel<<<(NG * NG + 255) / 256, 256>>>(out);
}